// round 5
// baseline (speedup 1.0000x reference)
#include <cuda_runtime.h>
#include <cstdint>
#include <cstddef>

#define BB 4
#define NN 4096
#define DD 256
#define RR 64
#define KK 16

#define FMA2(d, a, b) asm("fma.rn.f32x2 %0, %1, %2, %0;" : "+l"(d) : "l"(a), "l"(b))

// ---------------- device scratch (static; no runtime allocation) ----------------
__device__ float g_sp[(size_t)BB * NN * RR];
__device__ float g_dp[(size_t)BB * NN * RR];
__device__ float g_w[(size_t)BB * NN * KK];
__device__ int   g_idx[(size_t)BB * NN * KK];
__device__ float g_kstate[NN];
__device__ float g_kval[(size_t)NN * DD];
__device__ float g_nk[(size_t)NN * DD];
__device__ float g_nv[(size_t)BB * NN * DD];
__device__ float g_nb[(size_t)BB * NN * DD];
__device__ float g_ds[(size_t)BB * NN];

// ---------------- reductions ----------------
__device__ __forceinline__ float warpSum(float v) {
#pragma unroll
    for (int o = 16; o > 0; o >>= 1) v += __shfl_xor_sync(0xffffffffu, v, o);
    return v;
}
__device__ __forceinline__ float warpMax(float v) {
#pragma unroll
    for (int o = 16; o > 0; o >>= 1) v = fmaxf(v, __shfl_xor_sync(0xffffffffu, v, o));
    return v;
}
__device__ __forceinline__ float blockSum256(float v) {
    __shared__ float sh[8];
    int wid = threadIdx.x >> 5, lid = threadIdx.x & 31;
    v = warpSum(v);
    if (lid == 0) sh[wid] = v;
    __syncthreads();
    float r = sh[0] + sh[1] + sh[2] + sh[3] + sh[4] + sh[5] + sh[6] + sh[7];
    __syncthreads();
    return r;
}
__device__ __forceinline__ float blockMax256(float v) {
    __shared__ float sh[8];
    int wid = threadIdx.x >> 5, lid = threadIdx.x & 31;
    v = warpMax(v);
    if (lid == 0) sh[wid] = v;
    __syncthreads();
    float r = fmaxf(fmaxf(fmaxf(sh[0], sh[1]), fmaxf(sh[2], sh[3])),
                    fmaxf(fmaxf(sh[4], sh[5]), fmaxf(sh[6], sh[7])));
    __syncthreads();
    return r;
}

// ---------------- layernorm over rows of 256 ----------------
__global__ void __launch_bounds__(256) ln_kernel(const float* __restrict__ x, int srcMod,
                                                 const float* __restrict__ res,
                                                 const float* __restrict__ g,
                                                 const float* __restrict__ bt,
                                                 float* __restrict__ out) {
    int row = blockIdx.x;
    int srow = srcMod ? (row & (srcMod - 1)) : row;
    int t = threadIdx.x;
    float v = x[(size_t)srow * DD + t];
    if (res) v += res[(size_t)row * DD + t];
    float mean = blockSum256(v) * (1.f / DD);
    float d = v - mean;
    float var = blockSum256(d * d) * (1.f / DD);
    out[(size_t)row * DD + t] = d * rsqrtf(var + 1e-5f) * g[t] + bt[t];
}

// ---------------- signed softmax over rows of 4096 ----------------
__global__ void __launch_bounds__(256) ss_kernel(const float* __restrict__ x, int xB,
                                                 const float* __restrict__ add,
                                                 float* __restrict__ out) {
    int b = blockIdx.x;
    const float* xr = x + (xB ? 0 : (size_t)b * NN);
    const float* ar = add ? add + (size_t)b * NN : nullptr;
    int t = threadIdx.x;
    float v[16];
    float mx = 0.f;
#pragma unroll
    for (int i = 0; i < 16; i++) {
        float u = xr[t + 256 * i];
        if (ar) u += ar[t + 256 * i];
        v[i] = u;
        mx = fmaxf(mx, fabsf(u));
    }
    mx = blockMax256(mx);
    float s = 0.f;
#pragma unroll
    for (int i = 0; i < 16; i++) s += expf(fabsf(v[i]) - mx);
    s = blockSum256(s);
    float inv = 1.f / s;
#pragma unroll
    for (int i = 0; i < 16; i++) {
        float u = v[i];
        float sg = (u > 0.f) ? 1.f : ((u < 0.f) ? -1.f : 0.f);
        out[(size_t)b * NN + t + 256 * i] = sg * expf(fabsf(u) - mx) * inv;
    }
}

// ---------------- projection (round-1 version, measured 41us): X[rows,256] @ W[256,64] ----------------
__global__ void __launch_bounds__(256) proj_kernel(const float* __restrict__ X,
                                                   const float* __restrict__ W,
                                                   float* __restrict__ out, int nrows) {
    int gi = blockIdx.x * 256 + threadIdx.x;
    int row = gi >> 4, cq = gi & 15;
    if (row >= nrows) return;
    const float4* W4 = (const float4*)W;
    const float4* X4 = (const float4*)(X + (size_t)row * DD);
    float4 acc = make_float4(0.f, 0.f, 0.f, 0.f);
#pragma unroll 8
    for (int d4 = 0; d4 < 64; d4++) {
        float4 xv = X4[d4];
        float4 w;
        w = W4[(d4 * 4 + 0) * 16 + cq];
        acc.x = fmaf(xv.x, w.x, acc.x); acc.y = fmaf(xv.x, w.y, acc.y);
        acc.z = fmaf(xv.x, w.z, acc.z); acc.w = fmaf(xv.x, w.w, acc.w);
        w = W4[(d4 * 4 + 1) * 16 + cq];
        acc.x = fmaf(xv.y, w.x, acc.x); acc.y = fmaf(xv.y, w.y, acc.y);
        acc.z = fmaf(xv.y, w.z, acc.z); acc.w = fmaf(xv.y, w.w, acc.w);
        w = W4[(d4 * 4 + 2) * 16 + cq];
        acc.x = fmaf(xv.z, w.x, acc.x); acc.y = fmaf(xv.z, w.y, acc.y);
        acc.z = fmaf(xv.z, w.z, acc.z); acc.w = fmaf(xv.z, w.w, acc.w);
        w = W4[(d4 * 4 + 3) * 16 + cq];
        acc.x = fmaf(xv.w, w.x, acc.x); acc.y = fmaf(xv.w, w.y, acc.y);
        acc.z = fmaf(xv.w, w.z, acc.z); acc.w = fmaf(xv.w, w.w, acc.w);
    }
    ((float4*)out)[(size_t)row * 16 + cq] = acc;
}

// ---------------- fused score GEMM + exact top-16 (scores never hit HBM) ----------------
// Block owns 128 dst rows (n0..n0+127) of batch b; loops over 32 m-tiles of 128.
// Per thread: private exact top-16 of slice (row = t>>1, col-half = t&1).
// smem layout (floats): sD[64][132] dp-tile (resident), sS[64][132] sp-tile,
//                       sc[64][132] score half-tile, lkey[256*16], lpay[256*16].
#define SM_SD   0
#define SM_SS   (64 * 132)
#define SM_SC   (2 * 64 * 132)
#define SM_LKEY (3 * 64 * 132)
#define SM_LPAY (3 * 64 * 132 + 256 * 16)
#define SMEM_FUSED_BYTES ((3 * 64 * 132 + 2 * 256 * 16) * 4)

__global__ void __launch_bounds__(256) fused_score_topk(const float* __restrict__ dp,
                                                        const float* __restrict__ sp,
                                                        float* __restrict__ wOut,
                                                        int* __restrict__ idxOut,
                                                        int dpB, int spB) {
    extern __shared__ float sm[];
    float* sD = sm + SM_SD;
    float* sS = sm + SM_SS;
    float* sc = sm + SM_SC;
    unsigned int* lkey = (unsigned int*)(sm + SM_LKEY);
    unsigned int* lpay = (unsigned int*)(sm + SM_LPAY);

    int t = threadIdx.x;
    int tx = t & 15, ty = t >> 4;
    int b = blockIdx.y;
    int n0 = blockIdx.x * 128;
    const float* dpb = dp + (dpB ? 0 : (size_t)b * NN * RR);
    const float* spb = sp + (spB ? 0 : (size_t)b * NN * RR);

    // init private top-16 list
    unsigned int* myKey = lkey + t * 16;
    unsigned int* myPay = lpay + t * 16;
#pragma unroll
    for (int i = 0; i < 16; i++) { myKey[i] = 0u; myPay[i] = 0x7ffffffeu; }
    unsigned int thrK = 0u;

    // load resident dp tile: 128 rows x 64k, transposed sD[k][row]
#pragma unroll
    for (int i = 0; i < 8; i++) {
        int s = t + i * 256;
        int r = s >> 4, kq = s & 15;
        float4 v = *(const float4*)(dpb + (size_t)(n0 + r) * RR + kq * 4);
        sD[(kq * 4 + 0) * 132 + r] = v.x; sD[(kq * 4 + 1) * 132 + r] = v.y;
        sD[(kq * 4 + 2) * 132 + r] = v.z; sD[(kq * 4 + 3) * 132 + r] = v.w;
    }

    int rowOwn = t >> 1;        // 0..127 (tile-local dst row)
    int half = t & 1;           // col half 0/1
    int phase = t >> 7;         // which 64-row half this thread selects in

    for (int mt = 0; mt < 32; mt++) {
        int m0 = mt * 128;
        __syncthreads();
        // load sp tile
#pragma unroll
        for (int i = 0; i < 8; i++) {
            int s = t + i * 256;
            int r = s >> 4, kq = s & 15;
            float4 v = *(const float4*)(spb + (size_t)(m0 + r) * RR + kq * 4);
            sS[(kq * 4 + 0) * 132 + r] = v.x; sS[(kq * 4 + 1) * 132 + r] = v.y;
            sS[(kq * 4 + 2) * 132 + r] = v.z; sS[(kq * 4 + 3) * 132 + r] = v.w;
        }
        __syncthreads();

        // GEMM: acc[i][j] = rows {ty*4+i | 64+ty*4+(i-4)}, col pairs
        unsigned long long acc[8][4];
#pragma unroll
        for (int i = 0; i < 8; i++)
#pragma unroll
            for (int j = 0; j < 4; j++) acc[i][j] = 0ull;
#pragma unroll 4
        for (int k = 0; k < 64; k++) {
            const float* sk = sD + k * 132;
            float4 a0 = *(const float4*)&sk[ty * 4];
            float4 a1 = *(const float4*)&sk[64 + ty * 4];
            const float* bk = sS + k * 132;
            ulonglong2 bq0 = *(const ulonglong2*)&bk[tx * 4];
            ulonglong2 bq1 = *(const ulonglong2*)&bk[64 + tx * 4];
            unsigned long long bp0 = bq0.x, bp1 = bq0.y, bp2 = bq1.x, bp3 = bq1.y;
            float av[8] = {a0.x, a0.y, a0.z, a0.w, a1.x, a1.y, a1.z, a1.w};
#pragma unroll
            for (int i = 0; i < 8; i++) {
                unsigned long long ad;
                asm("mov.b64 %0, {%1, %1};" : "=l"(ad) : "r"(__float_as_uint(av[i])));
                FMA2(acc[i][0], ad, bp0);
                FMA2(acc[i][1], ad, bp1);
                FMA2(acc[i][2], ad, bp2);
                FMA2(acc[i][3], ad, bp3);
            }
        }

        // two half-tiles: write scores to smem, then private-slice selection
#pragma unroll
        for (int h = 0; h < 2; h++) {
            __syncthreads();   // sc free (prev selection done)
#pragma unroll
            for (int i = 0; i < 4; i++) {
                int ii = h * 4 + i;
                int row = ty * 4 + i;            // row within half
                float2 c0 = *(float2*)&acc[ii][0];
                float2 c1 = *(float2*)&acc[ii][1];
                float2 c2 = *(float2*)&acc[ii][2];
                float2 c3 = *(float2*)&acc[ii][3];
                *(float4*)&sc[row * 132 + tx * 4] =
                    make_float4(c0.x * 0.125f, c0.y * 0.125f, c1.x * 0.125f, c1.y * 0.125f);
                *(float4*)&sc[row * 132 + 64 + tx * 4] =
                    make_float4(c2.x * 0.125f, c2.y * 0.125f, c3.x * 0.125f, c3.y * 0.125f);
            }
            __syncthreads();
            if (phase == h) {
                const float* rowp = sc + (rowOwn & 63) * 132 + half * 64;
                int colBase = m0 + half * 64;
#pragma unroll 4
                for (int j4 = 0; j4 < 16; j4++) {
                    float4 v = *(const float4*)&rowp[j4 * 4];
                    float vs[4] = {v.x, v.y, v.z, v.w};
#pragma unroll
                    for (int c = 0; c < 4; c++) {
                        unsigned int ob = __float_as_uint(vs[c]);
                        unsigned int key = ob & 0x7fffffffu;
                        if (key > thrK) {
                            int pos = 15;
                            while (pos > 0 && myKey[pos - 1] < key) {
                                myKey[pos] = myKey[pos - 1];
                                myPay[pos] = myPay[pos - 1];
                                pos--;
                            }
                            myKey[pos] = key;
                            myPay[pos] = (unsigned int)(colBase + j4 * 4 + c) | (ob & 0x80000000u);
                            thrK = myKey[15];
                        }
                    }
                }
            }
        }
    }
    __syncthreads();

    // final merge: own slice vs sibling slice (t^1); rank = abs desc, ties -> lowest col
    unsigned int* oKey = lkey + (t ^ 1) * 16;
    unsigned int* oPay = lpay + (t ^ 1) * 16;
    int n = n0 + rowOwn;
    size_t outBase = ((size_t)b * NN + n) * KK;
#pragma unroll
    for (int i = 0; i < 16; i++) {
        unsigned int ki = myKey[i];
        unsigned int pi = myPay[i];
        int ci = (int)(pi & 0x7fffffffu);
        int rank = i;
#pragma unroll
        for (int j = 0; j < 16; j++) {
            unsigned int kj = oKey[j];
            int cj = (int)(oPay[j] & 0x7fffffffu);
            rank += (kj > ki) || (kj == ki && cj < ci);
        }
        if (rank < KK) {
            wOut[outBase + rank] = __uint_as_float(ki | (pi & 0x80000000u));
            idxOut[outBase + rank] = (ci < NN) ? ci : 0;
        }
    }
}

// ---------------- fused message aggregation + optional residual layernorm ----------------
__global__ void __launch_bounds__(256) msg_kernel(const float* __restrict__ w,
                                                  const int* __restrict__ idx,
                                                  const float* __restrict__ srcval, int srcB,
                                                  const float* __restrict__ state,
                                                  const float* __restrict__ res, int resMod,
                                                  const float* __restrict__ g,
                                                  const float* __restrict__ bt,
                                                  float* __restrict__ outVal,
                                                  float* __restrict__ dstate) {
    __shared__ float sW[16];
    __shared__ int sI[16];
    __shared__ float sNorm[16];
    size_t row = blockIdx.x;
    int b = (int)(row >> 12);
    int t = threadIdx.x;
    if (t < 16) { sW[t] = w[row * KK + t]; sI[t] = idx[row * KK + t]; }
    __syncthreads();
    if (t == 0) {
        float mx = 0.f;
        for (int k = 0; k < 16; k++) mx = fmaxf(mx, fabsf(sW[k]));
        float e[16];
        float s = 0.f;
        for (int k = 0; k < 16; k++) { e[k] = expf(fabsf(sW[k]) - mx); s += e[k]; }
        float inv = 1.f / s;
        float dsum = 0.f;
        for (int k = 0; k < 16; k++) {
            float u = sW[k];
            float sg = (u > 0.f) ? 1.f : ((u < 0.f) ? -1.f : 0.f);
            float wt = sg * e[k] * inv;
            if (state) {
                float st = state[(size_t)b * NN + sI[k]];
                float sp = fmaxf(st, 0.f) + log1pf(expf(-fabsf(st)));  // softplus
                wt *= sp;
            }
            sW[k] = wt;
            dsum += wt;
        }
        dstate[row] = dsum;
    }
    __syncthreads();
    const float* base = srcval + (srcB ? 0 : (size_t)b * NN * DD);
    int wid = t >> 5, lid = t & 31;
    for (int k = wid; k < 16; k += 8) {
        const float* v = base + (size_t)sI[k] * DD;
        float ss = 0.f;
#pragma unroll
        for (int i = lid; i < 256; i += 32) { float x = v[i]; ss += x * x; }
        ss = warpSum(ss);
        if (lid == 0) sNorm[k] = sqrtf(ss) + 1e-6f;
    }
    __syncthreads();
    float acc = 0.f;
#pragma unroll
    for (int k = 0; k < 16; k++) {
        const float* v = base + (size_t)sI[k] * DD;
        acc = fmaf(sW[k] / sNorm[k], v[t], acc);
    }
    if (g) {
        int srow = resMod ? (int)(row & (resMod - 1)) : (int)row;
        float v = res[(size_t)srow * DD + t] + acc;
        float mean = blockSum256(v) * (1.f / DD);
        float d = v - mean;
        float var = blockSum256(d * d) * (1.f / DD);
        outVal[row * (size_t)DD + t] = d * rsqrtf(var + 1e-5f) * g[t] + bt[t];
    } else {
        outVal[row * (size_t)DD + t] = acc;
    }
}

// ---------------- host orchestration ----------------
extern "C" void kernel_launch(void* const* d_in, const int* in_sizes, int n_in,
                              void* d_out, int out_size) {
    const float* b_state    = (const float*)d_in[0];
    const float* b_val      = (const float*)d_in[1];
    const float* init_state = (const float*)d_in[2];
    const float* init_val   = (const float*)d_in[3];
    const float* U_bk = (const float*)d_in[4];
    const float* V_bk = (const float*)d_in[5];
    const float* U_kb = (const float*)d_in[6];
    const float* V_kb = (const float*)d_in[7];
    const float* U_p  = (const float*)d_in[8];
    const float* V_p  = (const float*)d_in[9];
    const float* kn_g = (const float*)d_in[10];
    const float* kn_b = (const float*)d_in[11];
    const float* bn_g = (const float*)d_in[12];
    const float* bn_b = (const float*)d_in[13];
    const float* pn_g = (const float*)d_in[14];
    const float* pn_b = (const float*)d_in[15];

    float* out = (float*)d_out;
    float* o_rstate = out;
    float* o_rval   = o_rstate + (size_t)BB * NN;
    float* o_pstate = o_rval + (size_t)BB * NN * DD;
    float* o_pval   = o_pstate + (size_t)BB * NN;
    float* o_bds    = o_pval + (size_t)BB * NN * DD;
    float* o_bdv    = o_bds + (size_t)BB * NN;

    float *p_sp, *p_dp, *p_w, *p_kstate, *p_kval, *p_nk, *p_nv, *p_nb, *p_ds;
    int* p_idx;
    cudaGetSymbolAddress((void**)&p_sp, g_sp);
    cudaGetSymbolAddress((void**)&p_dp, g_dp);
    cudaGetSymbolAddress((void**)&p_w, g_w);
    cudaGetSymbolAddress((void**)&p_idx, g_idx);
    cudaGetSymbolAddress((void**)&p_kstate, g_kstate);
    cudaGetSymbolAddress((void**)&p_kval, g_kval);
    cudaGetSymbolAddress((void**)&p_nk, g_nk);
    cudaGetSymbolAddress((void**)&p_nv, g_nv);
    cudaGetSymbolAddress((void**)&p_nb, g_nb);
    cudaGetSymbolAddress((void**)&p_ds, g_ds);

    cudaFuncSetAttribute(fused_score_topk,
                         cudaFuncAttributeMaxDynamicSharedMemorySize, SMEM_FUSED_BYTES);

    dim3 fusedGrid(NN / 128, BB);

    // --- init ---
    ss_kernel<<<1, 256>>>(init_state, 1, nullptr, p_kstate);
    ln_kernel<<<NN, 256>>>(init_val, 0, nullptr, kn_g, kn_b, p_kval);
    ln_kernel<<<NN, 256>>>(p_kval, 0, nullptr, kn_g, kn_b, p_nk);

    // --- transition 1: B -> K ---
    proj_kernel<<<(BB * NN * 16) / 256, 256>>>(b_val, U_bk, p_sp, BB * NN);
    proj_kernel<<<(NN * 16) / 256, 256>>>(p_nk, V_bk, p_dp, NN);
    fused_score_topk<<<fusedGrid, 256, SMEM_FUSED_BYTES>>>(p_dp, p_sp, p_w, p_idx, 1, 0);
    msg_kernel<<<BB * NN, 256>>>(p_w, p_idx, b_val, 0, b_state,
                                 p_kval, NN, kn_g, kn_b, o_rval, p_ds);
    ss_kernel<<<BB, 256>>>(p_kstate, 1, p_ds, o_rstate);

    // --- propagation ---
    ln_kernel<<<BB * NN, 256>>>(o_rval, 0, nullptr, pn_g, pn_b, p_nv);
    proj_kernel<<<(BB * NN * 16) / 256, 256>>>(p_nv, U_p, p_sp, BB * NN);
    proj_kernel<<<(BB * NN * 16) / 256, 256>>>(p_nv, V_p, p_dp, BB * NN);
    fused_score_topk<<<fusedGrid, 256, SMEM_FUSED_BYTES>>>(p_dp, p_sp, p_w, p_idx, 0, 0);
    msg_kernel<<<BB * NN, 256>>>(p_w, p_idx, p_nv, 0, nullptr,
                                 o_rval, 0, kn_g, kn_b, o_pval, p_ds);
    ss_kernel<<<BB, 256>>>(o_rstate, 0, p_ds, o_pstate);

    // --- transition 2: K -> B (delta only) ---
    ln_kernel<<<BB * NN, 256>>>(o_pval, 0, nullptr, kn_g, kn_b, p_nv); // nk2
    ln_kernel<<<BB * NN, 256>>>(b_val, 0, nullptr, bn_g, bn_b, p_nb);  // nb
    proj_kernel<<<(BB * NN * 16) / 256, 256>>>(p_nv, U_kb, p_sp, BB * NN);
    proj_kernel<<<(BB * NN * 16) / 256, 256>>>(p_nb, V_kb, p_dp, BB * NN);
    fused_score_topk<<<fusedGrid, 256, SMEM_FUSED_BYTES>>>(p_dp, p_sp, p_w, p_idx, 0, 0);
    msg_kernel<<<BB * NN, 256>>>(p_w, p_idx, p_nv, 0, o_pstate,
                                 nullptr, 0, nullptr, nullptr, o_bdv, o_bds);
}

// round 6
// speedup vs baseline: 2.6295x; 2.6295x over previous
#include <cuda_runtime.h>
#include <cstdint>
#include <cstddef>

#define BB 4
#define NN 4096
#define DD 256
#define RR 64
#define KK 16

#define FMA2(d, a, b) asm("fma.rn.f32x2 %0, %1, %2, %0;" : "+l"(d) : "l"(a), "l"(b))

// ---------------- device scratch (static; no runtime allocation) ----------------
__device__ float g_scores[(size_t)BB * NN * NN];     // 256 MB
__device__ float g_sp[(size_t)BB * NN * RR];
__device__ float g_dp[(size_t)BB * NN * RR];
__device__ float g_w[(size_t)BB * NN * KK];
__device__ int   g_idx[(size_t)BB * NN * KK];
__device__ float g_kstate[NN];
__device__ float g_kval[(size_t)NN * DD];
__device__ float g_nk[(size_t)NN * DD];
__device__ float g_nv[(size_t)BB * NN * DD];
__device__ float g_nb[(size_t)BB * NN * DD];
__device__ float g_ds[(size_t)BB * NN];
__device__ float g_norms[(size_t)BB * NN];

// ---------------- reductions ----------------
__device__ __forceinline__ float warpSum(float v) {
#pragma unroll
    for (int o = 16; o > 0; o >>= 1) v += __shfl_xor_sync(0xffffffffu, v, o);
    return v;
}
__device__ __forceinline__ float warpMax(float v) {
#pragma unroll
    for (int o = 16; o > 0; o >>= 1) v = fmaxf(v, __shfl_xor_sync(0xffffffffu, v, o));
    return v;
}
__device__ __forceinline__ float blockSum256(float v) {
    __shared__ float sh[8];
    int wid = threadIdx.x >> 5, lid = threadIdx.x & 31;
    v = warpSum(v);
    if (lid == 0) sh[wid] = v;
    __syncthreads();
    float r = sh[0] + sh[1] + sh[2] + sh[3] + sh[4] + sh[5] + sh[6] + sh[7];
    __syncthreads();
    return r;
}
__device__ __forceinline__ float blockMax256(float v) {
    __shared__ float sh[8];
    int wid = threadIdx.x >> 5, lid = threadIdx.x & 31;
    v = warpMax(v);
    if (lid == 0) sh[wid] = v;
    __syncthreads();
    float r = fmaxf(fmaxf(fmaxf(sh[0], sh[1]), fmaxf(sh[2], sh[3])),
                    fmaxf(fmaxf(sh[4], sh[5]), fmaxf(sh[6], sh[7])));
    __syncthreads();
    return r;
}

// ---------------- layernorm over rows of 256 ----------------
__global__ void __launch_bounds__(256) ln_kernel(const float* __restrict__ x, int srcMod,
                                                 const float* __restrict__ res,
                                                 const float* __restrict__ g,
                                                 const float* __restrict__ bt,
                                                 float* __restrict__ out) {
    int row = blockIdx.x;
    int srow = srcMod ? (row & (srcMod - 1)) : row;
    int t = threadIdx.x;
    float v = x[(size_t)srow * DD + t];
    if (res) v += res[(size_t)row * DD + t];
    float mean = blockSum256(v) * (1.f / DD);
    float d = v - mean;
    float var = blockSum256(d * d) * (1.f / DD);
    out[(size_t)row * DD + t] = d * rsqrtf(var + 1e-5f) * g[t] + bt[t];
}

// ---------------- signed softmax over rows of 4096 ----------------
__global__ void __launch_bounds__(256) ss_kernel(const float* __restrict__ x, int xB,
                                                 const float* __restrict__ add,
                                                 float* __restrict__ out) {
    int b = blockIdx.x;
    const float* xr = x + (xB ? 0 : (size_t)b * NN);
    const float* ar = add ? add + (size_t)b * NN : nullptr;
    int t = threadIdx.x;
    float v[16];
    float mx = 0.f;
#pragma unroll
    for (int i = 0; i < 16; i++) {
        float u = xr[t + 256 * i];
        if (ar) u += ar[t + 256 * i];
        v[i] = u;
        mx = fmaxf(mx, fabsf(u));
    }
    mx = blockMax256(mx);
    float s = 0.f;
#pragma unroll
    for (int i = 0; i < 16; i++) s += expf(fabsf(v[i]) - mx);
    s = blockSum256(s);
    float inv = 1.f / s;
#pragma unroll
    for (int i = 0; i < 16; i++) {
        float u = v[i];
        float sg = (u > 0.f) ? 1.f : ((u < 0.f) ? -1.f : 0.f);
        out[(size_t)b * NN + t + 256 * i] = sg * expf(fabsf(u) - mx) * inv;
    }
}

// ---------------- projection v4: 4 rows x 4 cols per thread (2 B/FMA from L1) ----------------
__global__ void __launch_bounds__(256) proj_kernel(const float* __restrict__ X,
                                                   const float* __restrict__ W,
                                                   float* __restrict__ out, int nrows) {
    int gi = blockIdx.x * 256 + threadIdx.x;
    int rg = gi >> 4;            // row group of 4
    int cq = gi & 15;            // col group of 4
    int r0 = rg * 4;
    if (r0 >= nrows) return;
    const float4* W4 = (const float4*)W;
    const float4* X0 = (const float4*)(X + (size_t)(r0 + 0) * DD);
    const float4* X1 = (const float4*)(X + (size_t)(r0 + 1) * DD);
    const float4* X2 = (const float4*)(X + (size_t)(r0 + 2) * DD);
    const float4* X3 = (const float4*)(X + (size_t)(r0 + 3) * DD);
    float4 a0 = make_float4(0.f, 0.f, 0.f, 0.f);
    float4 a1 = a0, a2 = a0, a3 = a0;
#pragma unroll 4
    for (int d4 = 0; d4 < 64; d4++) {
        float4 x0 = X0[d4], x1 = X1[d4], x2 = X2[d4], x3 = X3[d4];
        float4 w;
        w = W4[(d4 * 4 + 0) * 16 + cq];
        a0.x = fmaf(x0.x, w.x, a0.x); a0.y = fmaf(x0.x, w.y, a0.y); a0.z = fmaf(x0.x, w.z, a0.z); a0.w = fmaf(x0.x, w.w, a0.w);
        a1.x = fmaf(x1.x, w.x, a1.x); a1.y = fmaf(x1.x, w.y, a1.y); a1.z = fmaf(x1.x, w.z, a1.z); a1.w = fmaf(x1.x, w.w, a1.w);
        a2.x = fmaf(x2.x, w.x, a2.x); a2.y = fmaf(x2.x, w.y, a2.y); a2.z = fmaf(x2.x, w.z, a2.z); a2.w = fmaf(x2.x, w.w, a2.w);
        a3.x = fmaf(x3.x, w.x, a3.x); a3.y = fmaf(x3.x, w.y, a3.y); a3.z = fmaf(x3.x, w.z, a3.z); a3.w = fmaf(x3.x, w.w, a3.w);
        w = W4[(d4 * 4 + 1) * 16 + cq];
        a0.x = fmaf(x0.y, w.x, a0.x); a0.y = fmaf(x0.y, w.y, a0.y); a0.z = fmaf(x0.y, w.z, a0.z); a0.w = fmaf(x0.y, w.w, a0.w);
        a1.x = fmaf(x1.y, w.x, a1.x); a1.y = fmaf(x1.y, w.y, a1.y); a1.z = fmaf(x1.y, w.z, a1.z); a1.w = fmaf(x1.y, w.w, a1.w);
        a2.x = fmaf(x2.y, w.x, a2.x); a2.y = fmaf(x2.y, w.y, a2.y); a2.z = fmaf(x2.y, w.z, a2.z); a2.w = fmaf(x2.y, w.w, a2.w);
        a3.x = fmaf(x3.y, w.x, a3.x); a3.y = fmaf(x3.y, w.y, a3.y); a3.z = fmaf(x3.y, w.z, a3.z); a3.w = fmaf(x3.y, w.w, a3.w);
        w = W4[(d4 * 4 + 2) * 16 + cq];
        a0.x = fmaf(x0.z, w.x, a0.x); a0.y = fmaf(x0.z, w.y, a0.y); a0.z = fmaf(x0.z, w.z, a0.z); a0.w = fmaf(x0.z, w.w, a0.w);
        a1.x = fmaf(x1.z, w.x, a1.x); a1.y = fmaf(x1.z, w.y, a1.y); a1.z = fmaf(x1.z, w.z, a1.z); a1.w = fmaf(x1.z, w.w, a1.w);
        a2.x = fmaf(x2.z, w.x, a2.x); a2.y = fmaf(x2.z, w.y, a2.y); a2.z = fmaf(x2.z, w.z, a2.z); a2.w = fmaf(x2.z, w.w, a2.w);
        a3.x = fmaf(x3.z, w.x, a3.x); a3.y = fmaf(x3.z, w.y, a3.y); a3.z = fmaf(x3.z, w.z, a3.z); a3.w = fmaf(x3.z, w.w, a3.w);
        w = W4[(d4 * 4 + 3) * 16 + cq];
        a0.x = fmaf(x0.w, w.x, a0.x); a0.y = fmaf(x0.w, w.y, a0.y); a0.z = fmaf(x0.w, w.z, a0.z); a0.w = fmaf(x0.w, w.w, a0.w);
        a1.x = fmaf(x1.w, w.x, a1.x); a1.y = fmaf(x1.w, w.y, a1.y); a1.z = fmaf(x1.w, w.z, a1.z); a1.w = fmaf(x1.w, w.w, a1.w);
        a2.x = fmaf(x2.w, w.x, a2.x); a2.y = fmaf(x2.w, w.y, a2.y); a2.z = fmaf(x2.w, w.z, a2.z); a2.w = fmaf(x2.w, w.w, a2.w);
        a3.x = fmaf(x3.w, w.x, a3.x); a3.y = fmaf(x3.w, w.y, a3.y); a3.z = fmaf(x3.w, w.z, a3.z); a3.w = fmaf(x3.w, w.w, a3.w);
    }
    float4* o = (float4*)out;
    o[(size_t)(r0 + 0) * 16 + cq] = a0;
    o[(size_t)(r0 + 1) * 16 + cq] = a1;
    o[(size_t)(r0 + 2) * 16 + cq] = a2;
    o[(size_t)(r0 + 3) * 16 + cq] = a3;
}

// ---------------- row L2-norms: norms[row] = sqrt(sum x^2) + 1e-6 ----------------
// One warp per row; reduction order identical to old msg_kernel (stride-32 lanes, warpSum).
__global__ void __launch_bounds__(256) rnorm_kernel(const float* __restrict__ X,
                                                    float* __restrict__ norms) {
    int row = blockIdx.x * 8 + (threadIdx.x >> 5);
    int lid = threadIdx.x & 31;
    const float* v = X + (size_t)row * DD;
    float ss = 0.f;
#pragma unroll
    for (int i = lid; i < 256; i += 32) { float x = v[i]; ss += x * x; }
    ss = warpSum(ss);
    if (lid == 0) norms[row] = sqrtf(ss) + 1e-6f;
}

// ---------------- score GEMM (round-2 f32x2 version, FMA2-pipe-bound) ----------------
__global__ void __launch_bounds__(256) score_gemm_kernel(const float* __restrict__ dp,
                                                         const float* __restrict__ sp,
                                                         float* __restrict__ out,
                                                         int dpB, int spB) {
    __shared__ float sD[32][132];
    __shared__ float sS[32][132];
    int b = blockIdx.z;
    int n0 = blockIdx.y * 128;
    int m0 = blockIdx.x * 128;
    const float* dpb = dp + (dpB ? 0 : (size_t)b * NN * RR);
    const float* spb = sp + (spB ? 0 : (size_t)b * NN * RR);
    int t = threadIdx.x;
    int tx = t & 15, ty = t >> 4;
    unsigned long long acc[8][4];
#pragma unroll
    for (int i = 0; i < 8; i++)
#pragma unroll
        for (int j = 0; j < 4; j++) acc[i][j] = 0ull;

    for (int kc = 0; kc < 2; kc++) {
        __syncthreads();
#pragma unroll
        for (int i = 0; i < 4; i++) {
            int s = t + i * 256;
            int r = s >> 3;
            int kq = s & 7;
            float4 dv = *(const float4*)(dpb + (size_t)(n0 + r) * RR + kc * 32 + kq * 4);
            sD[kq * 4 + 0][r] = dv.x; sD[kq * 4 + 1][r] = dv.y;
            sD[kq * 4 + 2][r] = dv.z; sD[kq * 4 + 3][r] = dv.w;
            float4 sv = *(const float4*)(spb + (size_t)(m0 + r) * RR + kc * 32 + kq * 4);
            sS[kq * 4 + 0][r] = sv.x; sS[kq * 4 + 1][r] = sv.y;
            sS[kq * 4 + 2][r] = sv.z; sS[kq * 4 + 3][r] = sv.w;
        }
        __syncthreads();
#pragma unroll 4
        for (int k = 0; k < 32; k++) {
            float4 a0 = *(const float4*)&sD[k][ty * 4];
            float4 a1 = *(const float4*)&sD[k][64 + ty * 4];
            ulonglong2 bq0 = *(const ulonglong2*)&sS[k][tx * 4];
            ulonglong2 bq1 = *(const ulonglong2*)&sS[k][64 + tx * 4];
            unsigned long long bp0 = bq0.x, bp1 = bq0.y, bp2 = bq1.x, bp3 = bq1.y;
            float av[8] = {a0.x, a0.y, a0.z, a0.w, a1.x, a1.y, a1.z, a1.w};
#pragma unroll
            for (int i = 0; i < 8; i++) {
                unsigned long long ad;
                asm("mov.b64 %0, {%1, %1};" : "=l"(ad) : "r"(__float_as_uint(av[i])));
                FMA2(acc[i][0], ad, bp0);
                FMA2(acc[i][1], ad, bp1);
                FMA2(acc[i][2], ad, bp2);
                FMA2(acc[i][3], ad, bp3);
            }
        }
    }
    float* outb = out + ((size_t)b * NN + n0) * NN + m0;
#pragma unroll
    for (int i = 0; i < 8; i++) {
        int n = (i < 4) ? (ty * 4 + i) : (64 + ty * 4 + (i - 4));
        float2 c0 = *(float2*)&acc[i][0];
        float2 c1 = *(float2*)&acc[i][1];
        float2 c2 = *(float2*)&acc[i][2];
        float2 c3 = *(float2*)&acc[i][3];
        float4 r0 = make_float4(c0.x * 0.125f, c0.y * 0.125f, c1.x * 0.125f, c1.y * 0.125f);
        float4 r1 = make_float4(c2.x * 0.125f, c2.y * 0.125f, c3.x * 0.125f, c3.y * 0.125f);
        *(float4*)(outb + (size_t)n * NN + tx * 4) = r0;
        *(float4*)(outb + (size_t)n * NN + 64 + tx * 4) = r1;
    }
}

// ---------------- top-16 by |score| per row: threshold + rank selection ----------------
__global__ void __launch_bounds__(256) topk_kernel(const float* __restrict__ scores,
                                                   float* __restrict__ wOut,
                                                   int* __restrict__ idxOut) {
    __shared__ unsigned int sVal[256];
    __shared__ int sColA[256];
    __shared__ unsigned int warp2[8];
    __shared__ int sCnt;
    size_t row = blockIdx.x;
    const float* sr = scores + row * (size_t)NN;
    int t = threadIdx.x;
    int lid = t & 31, wid = t >> 5;

    float vv[16];
    unsigned int kk[16];
#pragma unroll
    for (int i = 0; i < 4; i++) {
        float4 v = *(const float4*)&sr[t * 4 + i * 1024];
        vv[i * 4 + 0] = v.x; vv[i * 4 + 1] = v.y; vv[i * 4 + 2] = v.z; vv[i * 4 + 3] = v.w;
    }
#pragma unroll
    for (int e = 0; e < 16; e++) kk[e] = __float_as_uint(vv[e]) & 0x7fffffffu;

    unsigned int m1 = 0u, m2 = 0u;
#pragma unroll
    for (int e = 0; e < 16; e++) {
        unsigned int k = kk[e];
        if (k > m1) { m2 = m1; m1 = k; }
        else if (k > m2) { m2 = k; }
    }
#pragma unroll
    for (int o = 16; o > 0; o >>= 1) {
        unsigned int o1 = __shfl_xor_sync(0xffffffffu, m1, o);
        unsigned int o2 = __shfl_xor_sync(0xffffffffu, m2, o);
        if (o1 > m1) { m2 = (m1 > o2) ? m1 : o2; m1 = o1; }
        else { m2 = (m2 > o1) ? m2 : o1; }
    }
    if (lid == 0) warp2[wid] = m2;
    if (t == 0) sCnt = 0;
    __syncthreads();
    unsigned int T = warp2[0];
#pragma unroll
    for (int u = 1; u < 8; u++) T = (warp2[u] < T) ? warp2[u] : T;

#pragma unroll
    for (int e = 0; e < 16; e++) {
        if (kk[e] >= T) {
            int p = atomicAdd(&sCnt, 1);
            if (p < 256) {
                sVal[p] = __float_as_uint(vv[e]);
                sColA[p] = t * 4 + (e & 3) + (e >> 2) * 1024;
            }
        }
    }
    __syncthreads();
    int C = sCnt;
    if (C <= 256) {
        if (t < C) {
            unsigned int vb = sVal[t];
            unsigned int ki = vb & 0x7fffffffu;
            int ci = sColA[t];
            int rank = 0;
            for (int j = 0; j < C; j++) {
                unsigned int vj = sVal[j];
                unsigned int kj = vj & 0x7fffffffu;
                int cj = sColA[j];
                rank += (kj > ki) || (kj == ki && cj < ci);
            }
            if (rank < KK) {
                wOut[row * KK + rank] = __uint_as_float(vb);
                idxOut[row * KK + rank] = ci;
            }
        }
    } else if (t == 0) {
        unsigned int bk[16]; float bv[16]; int bc[16];
        int cnt = 0;
        for (int c = 0; c < NN; c++) {
            float val = sr[c];
            unsigned int key = __float_as_uint(val) & 0x7fffffffu;
            if (cnt == 16 && key <= bk[15]) continue;
            int pos = (cnt < 16) ? cnt : 15;
            while (pos > 0 && bk[pos - 1] < key) {
                bk[pos] = bk[pos - 1]; bv[pos] = bv[pos - 1]; bc[pos] = bc[pos - 1];
                pos--;
            }
            bk[pos] = key; bv[pos] = val; bc[pos] = c;
            if (cnt < 16) cnt++;
        }
        for (int k = 0; k < KK; k++) {
            wOut[row * KK + k] = bv[k];
            idxOut[row * KK + k] = bc[k];
        }
    }
}

// ---------------- fused message aggregation (precomputed norms) + optional residual LN ----------------
__global__ void __launch_bounds__(256) msg_kernel(const float* __restrict__ w,
                                                  const int* __restrict__ idx,
                                                  const float* __restrict__ srcval, int srcB,
                                                  const float* __restrict__ norms,
                                                  const float* __restrict__ state,
                                                  const float* __restrict__ res, int resMod,
                                                  const float* __restrict__ g,
                                                  const float* __restrict__ bt,
                                                  float* __restrict__ outVal,
                                                  float* __restrict__ dstate) {
    __shared__ float sW[16];
    __shared__ int sI[16];
    size_t row = blockIdx.x;
    int b = (int)(row >> 12);
    int t = threadIdx.x;
    if (t < 16) { sW[t] = w[row * KK + t]; sI[t] = idx[row * KK + t]; }
    __syncthreads();
    if (t == 0) {
        float mx = 0.f;
        for (int k = 0; k < 16; k++) mx = fmaxf(mx, fabsf(sW[k]));
        float e[16];
        float s = 0.f;
        for (int k = 0; k < 16; k++) { e[k] = expf(fabsf(sW[k]) - mx); s += e[k]; }
        float inv = 1.f / s;
        float dsum = 0.f;
        int nbase = srcB ? 0 : (b << 12);
        for (int k = 0; k < 16; k++) {
            float u = sW[k];
            float sg = (u > 0.f) ? 1.f : ((u < 0.f) ? -1.f : 0.f);
            float wt = sg * e[k] * inv;
            if (state) {
                float st = state[(size_t)b * NN + sI[k]];
                float sp = fmaxf(st, 0.f) + log1pf(expf(-fabsf(st)));  // softplus
                wt *= sp;
            }
            dsum += wt;
            sW[k] = wt / norms[nbase + sI[k]];
        }
        dstate[row] = dsum;
    }
    __syncthreads();
    const float* base = srcval + (srcB ? 0 : (size_t)b * NN * DD);
    float acc = 0.f;
#pragma unroll
    for (int k = 0; k < 16; k++) {
        const float* v = base + (size_t)sI[k] * DD;
        acc = fmaf(sW[k], v[t], acc);
    }
    if (g) {
        int srow = resMod ? (int)(row & (resMod - 1)) : (int)row;
        float v = res[(size_t)srow * DD + t] + acc;
        float mean = blockSum256(v) * (1.f / DD);
        float d = v - mean;
        float var = blockSum256(d * d) * (1.f / DD);
        outVal[row * (size_t)DD + t] = d * rsqrtf(var + 1e-5f) * g[t] + bt[t];
    } else {
        outVal[row * (size_t)DD + t] = acc;
    }
}

// ---------------- host orchestration ----------------
extern "C" void kernel_launch(void* const* d_in, const int* in_sizes, int n_in,
                              void* d_out, int out_size) {
    const float* b_state    = (const float*)d_in[0];
    const float* b_val      = (const float*)d_in[1];
    const float* init_state = (const float*)d_in[2];
    const float* init_val   = (const float*)d_in[3];
    const float* U_bk = (const float*)d_in[4];
    const float* V_bk = (const float*)d_in[5];
    const float* U_kb = (const float*)d_in[6];
    const float* V_kb = (const float*)d_in[7];
    const float* U_p  = (const float*)d_in[8];
    const float* V_p  = (const float*)d_in[9];
    const float* kn_g = (const float*)d_in[10];
    const float* kn_b = (const float*)d_in[11];
    const float* bn_g = (const float*)d_in[12];
    const float* bn_b = (const float*)d_in[13];
    const float* pn_g = (const float*)d_in[14];
    const float* pn_b = (const float*)d_in[15];

    float* out = (float*)d_out;
    float* o_rstate = out;
    float* o_rval   = o_rstate + (size_t)BB * NN;
    float* o_pstate = o_rval + (size_t)BB * NN * DD;
    float* o_pval   = o_pstate + (size_t)BB * NN;
    float* o_bds    = o_pval + (size_t)BB * NN * DD;
    float* o_bdv    = o_bds + (size_t)BB * NN;

    float *p_scores, *p_sp, *p_dp, *p_w, *p_kstate, *p_kval, *p_nk, *p_nv, *p_nb, *p_ds, *p_norms;
    int* p_idx;
    cudaGetSymbolAddress((void**)&p_scores, g_scores);
    cudaGetSymbolAddress((void**)&p_sp, g_sp);
    cudaGetSymbolAddress((void**)&p_dp, g_dp);
    cudaGetSymbolAddress((void**)&p_w, g_w);
    cudaGetSymbolAddress((void**)&p_idx, g_idx);
    cudaGetSymbolAddress((void**)&p_kstate, g_kstate);
    cudaGetSymbolAddress((void**)&p_kval, g_kval);
    cudaGetSymbolAddress((void**)&p_nk, g_nk);
    cudaGetSymbolAddress((void**)&p_nv, g_nv);
    cudaGetSymbolAddress((void**)&p_nb, g_nb);
    cudaGetSymbolAddress((void**)&p_ds, g_ds);
    cudaGetSymbolAddress((void**)&p_norms, g_norms);

    dim3 gemmGrid(32, 32, 4);

    // --- init ---
    ss_kernel<<<1, 256>>>(init_state, 1, nullptr, p_kstate);
    ln_kernel<<<NN, 256>>>(init_val, 0, nullptr, kn_g, kn_b, p_kval);
    ln_kernel<<<NN, 256>>>(p_kval, 0, nullptr, kn_g, kn_b, p_nk);

    // --- transition 1: B -> K ---
    proj_kernel<<<(BB * NN * 4) / 256, 256>>>(b_val, U_bk, p_sp, BB * NN);
    proj_kernel<<<(NN * 4) / 256, 256>>>(p_nk, V_bk, p_dp, NN);
    rnorm_kernel<<<BB * NN / 8, 256>>>(b_val, p_norms);
    score_gemm_kernel<<<gemmGrid, 256>>>(p_dp, p_sp, p_scores, 1, 0);
    topk_kernel<<<BB * NN, 256>>>(p_scores, p_w, p_idx);
    msg_kernel<<<BB * NN, 256>>>(p_w, p_idx, b_val, 0, p_norms, b_state,
                                 p_kval, NN, kn_g, kn_b, o_rval, p_ds);
    ss_kernel<<<BB, 256>>>(p_kstate, 1, p_ds, o_rstate);

    // --- propagation ---
    ln_kernel<<<BB * NN, 256>>>(o_rval, 0, nullptr, pn_g, pn_b, p_nv);
    proj_kernel<<<(BB * NN * 4) / 256, 256>>>(p_nv, U_p, p_sp, BB * NN);
    proj_kernel<<<(BB * NN * 4) / 256, 256>>>(p_nv, V_p, p_dp, BB * NN);
    rnorm_kernel<<<BB * NN / 8, 256>>>(p_nv, p_norms);
    score_gemm_kernel<<<gemmGrid, 256>>>(p_dp, p_sp, p_scores, 0, 0);
    topk_kernel<<<BB * NN, 256>>>(p_scores, p_w, p_idx);
    msg_kernel<<<BB * NN, 256>>>(p_w, p_idx, p_nv, 0, p_norms, nullptr,
                                 o_rval, 0, kn_g, kn_b, o_pval, p_ds);
    ss_kernel<<<BB, 256>>>(o_rstate, 0, p_ds, o_pstate);

    // --- transition 2: K -> B (delta only) ---
    ln_kernel<<<BB * NN, 256>>>(o_pval, 0, nullptr, kn_g, kn_b, p_nv); // nk2
    ln_kernel<<<BB * NN, 256>>>(b_val, 0, nullptr, bn_g, bn_b, p_nb);  // nb
    proj_kernel<<<(BB * NN * 4) / 256, 256>>>(p_nv, U_kb, p_sp, BB * NN);
    proj_kernel<<<(BB * NN * 4) / 256, 256>>>(p_nb, V_kb, p_dp, BB * NN);
    rnorm_kernel<<<BB * NN / 8, 256>>>(p_nv, p_norms);
    score_gemm_kernel<<<gemmGrid, 256>>>(p_dp, p_sp, p_scores, 0, 0);
    topk_kernel<<<BB * NN, 256>>>(p_scores, p_w, p_idx);
    msg_kernel<<<BB * NN, 256>>>(p_w, p_idx, p_nv, 0, p_norms, o_pstate,
                                 nullptr, 0, nullptr, nullptr, o_bdv, o_bds);
}

// round 11
// speedup vs baseline: 2.7472x; 1.0448x over previous
#include <cuda_runtime.h>
#include <cuda_bf16.h>
#include <mma.h>
#include <cstdint>
#include <cstddef>

#define BB 4
#define NN 4096
#define DD 256
#define RR 64
#define KK 16

// ---------------- device scratch (static; no runtime allocation) ----------------
__device__ float g_scores[(size_t)BB * NN * NN];     // 256 MB (approx scores)
__device__ float g_spf[(size_t)BB * NN * RR];
__device__ float g_dpf[(size_t)BB * NN * RR];
__device__ __nv_bfloat16 g_sph[(size_t)BB * NN * RR];
__device__ __nv_bfloat16 g_spl[(size_t)BB * NN * RR];
__device__ __nv_bfloat16 g_dph[(size_t)BB * NN * RR];
__device__ __nv_bfloat16 g_dpl[(size_t)BB * NN * RR];
__device__ float g_w[(size_t)BB * NN * KK];
__device__ int   g_idx[(size_t)BB * NN * KK];
__device__ float g_kstate[NN];
__device__ float g_kval[(size_t)NN * DD];
__device__ float g_nk[(size_t)NN * DD];
__device__ float g_nv[(size_t)BB * NN * DD];
__device__ float g_nb[(size_t)BB * NN * DD];
__device__ float g_ds[(size_t)BB * NN];

// ---------------- reductions ----------------
__device__ __forceinline__ float warpSum(float v) {
#pragma unroll
    for (int o = 16; o > 0; o >>= 1) v += __shfl_xor_sync(0xffffffffu, v, o);
    return v;
}
__device__ __forceinline__ float warpMax(float v) {
#pragma unroll
    for (int o = 16; o > 0; o >>= 1) v = fmaxf(v, __shfl_xor_sync(0xffffffffu, v, o));
    return v;
}
__device__ __forceinline__ float blockSum256(float v) {
    __shared__ float sh[8];
    int wid = threadIdx.x >> 5, lid = threadIdx.x & 31;
    v = warpSum(v);
    if (lid == 0) sh[wid] = v;
    __syncthreads();
    float r = sh[0] + sh[1] + sh[2] + sh[3] + sh[4] + sh[5] + sh[6] + sh[7];
    __syncthreads();
    return r;
}
__device__ __forceinline__ float blockMax256(float v) {
    __shared__ float sh[8];
    int wid = threadIdx.x >> 5, lid = threadIdx.x & 31;
    v = warpMax(v);
    if (lid == 0) sh[wid] = v;
    __syncthreads();
    float r = fmaxf(fmaxf(fmaxf(sh[0], sh[1]), fmaxf(sh[2], sh[3])),
                    fmaxf(fmaxf(sh[4], sh[5]), fmaxf(sh[6], sh[7])));
    __syncthreads();
    return r;
}

// ---------------- layernorm over rows of 256 ----------------
__global__ void __launch_bounds__(256) ln_kernel(const float* __restrict__ x, int srcMod,
                                                 const float* __restrict__ res,
                                                 const float* __restrict__ g,
                                                 const float* __restrict__ bt,
                                                 float* __restrict__ out) {
    int row = blockIdx.x;
    int srow = srcMod ? (row & (srcMod - 1)) : row;
    int t = threadIdx.x;
    float v = x[(size_t)srow * DD + t];
    if (res) v += res[(size_t)row * DD + t];
    float mean = blockSum256(v) * (1.f / DD);
    float d = v - mean;
    float var = blockSum256(d * d) * (1.f / DD);
    out[(size_t)row * DD + t] = d * rsqrtf(var + 1e-5f) * g[t] + bt[t];
}

// ---------------- signed softmax over rows of 4096 ----------------
__global__ void __launch_bounds__(256) ss_kernel(const float* __restrict__ x, int xB,
                                                 const float* __restrict__ add,
                                                 float* __restrict__ out) {
    int b = blockIdx.x;
    const float* xr = x + (xB ? 0 : (size_t)b * NN);
    const float* ar = add ? add + (size_t)b * NN : nullptr;
    int t = threadIdx.x;
    float v[16];
    float mx = 0.f;
#pragma unroll
    for (int i = 0; i < 16; i++) {
        float u = xr[t + 256 * i];
        if (ar) u += ar[t + 256 * i];
        v[i] = u;
        mx = fmaxf(mx, fabsf(u));
    }
    mx = blockMax256(mx);
    float s = 0.f;
#pragma unroll
    for (int i = 0; i < 16; i++) s += expf(fabsf(v[i]) - mx);
    s = blockSum256(s);
    float inv = 1.f / s;
#pragma unroll
    for (int i = 0; i < 16; i++) {
        float u = v[i];
        float sg = (u > 0.f) ? 1.f : ((u < 0.f) ? -1.f : 0.f);
        out[(size_t)b * NN + t + 256 * i] = sg * expf(fabsf(u) - mx) * inv;
    }
}

// ---------------- projection: X[rows,256] @ W[256,64] -> fp32 + split bf16 (hi, lo) ----------------
__global__ void __launch_bounds__(256) proj_kernel(const float* __restrict__ X,
                                                   const float* __restrict__ W,
                                                   float* __restrict__ outF,
                                                   __nv_bfloat16* __restrict__ outH,
                                                   __nv_bfloat16* __restrict__ outL,
                                                   int nrows) {
    int gi = blockIdx.x * 256 + threadIdx.x;
    int row = gi >> 4, cq = gi & 15;
    if (row >= nrows) return;
    const float4* W4 = (const float4*)W;
    const float4* X4 = (const float4*)(X + (size_t)row * DD);
    float4 acc = make_float4(0.f, 0.f, 0.f, 0.f);
#pragma unroll 8
    for (int d4 = 0; d4 < 64; d4++) {
        float4 xv = X4[d4];
        float4 w;
        w = W4[(d4 * 4 + 0) * 16 + cq];
        acc.x = fmaf(xv.x, w.x, acc.x); acc.y = fmaf(xv.x, w.y, acc.y);
        acc.z = fmaf(xv.x, w.z, acc.z); acc.w = fmaf(xv.x, w.w, acc.w);
        w = W4[(d4 * 4 + 1) * 16 + cq];
        acc.x = fmaf(xv.y, w.x, acc.x); acc.y = fmaf(xv.y, w.y, acc.y);
        acc.z = fmaf(xv.y, w.z, acc.z); acc.w = fmaf(xv.y, w.w, acc.w);
        w = W4[(d4 * 4 + 2) * 16 + cq];
        acc.x = fmaf(xv.z, w.x, acc.x); acc.y = fmaf(xv.z, w.y, acc.y);
        acc.z = fmaf(xv.z, w.z, acc.z); acc.w = fmaf(xv.z, w.w, acc.w);
        w = W4[(d4 * 4 + 3) * 16 + cq];
        acc.x = fmaf(xv.w, w.x, acc.x); acc.y = fmaf(xv.w, w.y, acc.y);
        acc.z = fmaf(xv.w, w.z, acc.z); acc.w = fmaf(xv.w, w.w, acc.w);
    }
    ((float4*)outF)[(size_t)row * 16 + cq] = acc;
    __nv_bfloat16 hx = __float2bfloat16(acc.x);
    __nv_bfloat16 hy = __float2bfloat16(acc.y);
    __nv_bfloat16 hz = __float2bfloat16(acc.z);
    __nv_bfloat16 hw = __float2bfloat16(acc.w);
    __nv_bfloat16 lx = __float2bfloat16(acc.x - __bfloat162float(hx));
    __nv_bfloat16 ly = __float2bfloat16(acc.y - __bfloat162float(hy));
    __nv_bfloat16 lz = __float2bfloat16(acc.z - __bfloat162float(hz));
    __nv_bfloat16 lw = __float2bfloat16(acc.w - __bfloat162float(hw));
    size_t base = (size_t)row * RR + cq * 4;
    __nv_bfloat162* oh = (__nv_bfloat162*)(outH + base);
    __nv_bfloat162* ol = (__nv_bfloat162*)(outL + base);
    oh[0] = __nv_bfloat162(hx, hy); oh[1] = __nv_bfloat162(hz, hw);
    ol[0] = __nv_bfloat162(lx, ly); ol[1] = __nv_bfloat162(lz, lw);
}

// ---------------- WMMA approx score GEMM (hh + hl + lh) ----------------
#define LDS_B 72
#define TILE_BYTES (128 * LDS_B * 2)
#define WSM_AH 0
#define WSM_AL (TILE_BYTES)
#define WSM_BH (2 * TILE_BYTES)
#define WSM_BL (3 * TILE_BYTES)
#define WSM_TOTAL (4 * TILE_BYTES)

using namespace nvcuda;

__global__ void __launch_bounds__(256) wmma_score_kernel(const __nv_bfloat16* __restrict__ dph,
                                                         const __nv_bfloat16* __restrict__ dpl,
                                                         const __nv_bfloat16* __restrict__ sph,
                                                         const __nv_bfloat16* __restrict__ spl,
                                                         float* __restrict__ out,
                                                         int dpB, int spB) {
    extern __shared__ char smemRaw[];
    __nv_bfloat16* sAh = (__nv_bfloat16*)(smemRaw + WSM_AH);
    __nv_bfloat16* sAl = (__nv_bfloat16*)(smemRaw + WSM_AL);
    __nv_bfloat16* sBh = (__nv_bfloat16*)(smemRaw + WSM_BH);
    __nv_bfloat16* sBl = (__nv_bfloat16*)(smemRaw + WSM_BL);

    int t = threadIdx.x;
    int w = t >> 5;
    int wn = w >> 1;
    int wm = w & 1;
    int n0 = blockIdx.x * 128;
    int b = blockIdx.y;
    const __nv_bfloat16* dphb = dph + (dpB ? 0 : (size_t)b * NN * RR);
    const __nv_bfloat16* dplb = dpl + (dpB ? 0 : (size_t)b * NN * RR);
    const __nv_bfloat16* sphb = sph + (spB ? 0 : (size_t)b * NN * RR);
    const __nv_bfloat16* splb = spl + (spB ? 0 : (size_t)b * NN * RR);

#pragma unroll
    for (int i = 0; i < 4; i++) {
        int s = t + i * 256;
        int r = s >> 3, q = s & 7;
        *(float4*)&sAh[r * LDS_B + q * 8] = *(const float4*)(dphb + (size_t)(n0 + r) * RR + q * 8);
        *(float4*)&sAl[r * LDS_B + q * 8] = *(const float4*)(dplb + (size_t)(n0 + r) * RR + q * 8);
    }

    for (int mt = 0; mt < 32; mt++) {
        int m0 = mt * 128;
        __syncthreads();
#pragma unroll
        for (int i = 0; i < 4; i++) {
            int s = t + i * 256;
            int r = s >> 3, q = s & 7;
            *(float4*)&sBh[r * LDS_B + q * 8] = *(const float4*)(sphb + (size_t)(m0 + r) * RR + q * 8);
            *(float4*)&sBl[r * LDS_B + q * 8] = *(const float4*)(splb + (size_t)(m0 + r) * RR + q * 8);
        }
        __syncthreads();

        wmma::fragment<wmma::accumulator, 16, 16, 16, float> acc[2][4];
#pragma unroll
        for (int i = 0; i < 2; i++)
#pragma unroll
            for (int j = 0; j < 4; j++) wmma::fill_fragment(acc[i][j], 0.f);

#pragma unroll
        for (int ks = 0; ks < 4; ks++) {
            wmma::fragment<wmma::matrix_a, 16, 16, 16, __nv_bfloat16, wmma::row_major> ah0, ah1, al0, al1;
            wmma::load_matrix_sync(ah0, &sAh[(wn * 32 + 0) * LDS_B + ks * 16], LDS_B);
            wmma::load_matrix_sync(ah1, &sAh[(wn * 32 + 16) * LDS_B + ks * 16], LDS_B);
            wmma::load_matrix_sync(al0, &sAl[(wn * 32 + 0) * LDS_B + ks * 16], LDS_B);
            wmma::load_matrix_sync(al1, &sAl[(wn * 32 + 16) * LDS_B + ks * 16], LDS_B);
#pragma unroll
            for (int j = 0; j < 4; j++) {
                wmma::fragment<wmma::matrix_b, 16, 16, 16, __nv_bfloat16, wmma::col_major> bh, bl;
                wmma::load_matrix_sync(bh, &sBh[(wm * 64 + j * 16) * LDS_B + ks * 16], LDS_B);
                wmma::load_matrix_sync(bl, &sBl[(wm * 64 + j * 16) * LDS_B + ks * 16], LDS_B);
                wmma::mma_sync(acc[0][j], ah0, bh, acc[0][j]);
                wmma::mma_sync(acc[1][j], ah1, bh, acc[1][j]);
                wmma::mma_sync(acc[0][j], ah0, bl, acc[0][j]);
                wmma::mma_sync(acc[1][j], ah1, bl, acc[1][j]);
                wmma::mma_sync(acc[0][j], al0, bh, acc[0][j]);
                wmma::mma_sync(acc[1][j], al1, bh, acc[1][j]);
            }
        }

#pragma unroll
        for (int i = 0; i < 2; i++)
#pragma unroll
            for (int j = 0; j < 4; j++) {
#pragma unroll
                for (int e = 0; e < acc[i][j].num_elements; e++) acc[i][j].x[e] *= 0.125f;
                float* op = out + ((size_t)b * NN + n0 + wn * 32 + i * 16) * NN
                              + m0 + wm * 64 + j * 16;
                wmma::store_matrix_sync(op, acc[i][j], NN, wmma::mem_row_major);
            }
    }
}

// ---------------- top-16: approx filter (2% margin) + EXACT fp32 re-score + rank select ----------------
__device__ __forceinline__ float dot64(const float4* a4, const float* bp) {
    const float4* b4 = (const float4*)bp;
    float s = 0.f;
#pragma unroll
    for (int q = 0; q < 16; q++) {
        float4 a = a4[q], b = b4[q];
        s = fmaf(a.x, b.x, s); s = fmaf(a.y, b.y, s);
        s = fmaf(a.z, b.z, s); s = fmaf(a.w, b.w, s);
    }
    return s * 0.125f;
}

__global__ void __launch_bounds__(256) topk_kernel(const float* __restrict__ approx,
                                                   const float* __restrict__ dpf,
                                                   const float* __restrict__ spf,
                                                   int dpB, int spB,
                                                   float* __restrict__ wOut,
                                                   int* __restrict__ idxOut) {
    __shared__ float sEx[4096];          // fallback exact row (rarely used)
    __shared__ float sDp[64];
    __shared__ unsigned int sVal[256];
    __shared__ int sColA[256];
    __shared__ unsigned int warp2[8];
    __shared__ int sCnt;
    size_t row = blockIdx.x;
    int b = (int)(row >> 12);
    int n = (int)(row & (NN - 1));
    const float* sr = approx + row * (size_t)NN;
    const float* dpRow = dpf + (dpB ? 0 : (size_t)b * NN * RR) + (size_t)n * RR;
    const float* spb = spf + (spB ? 0 : (size_t)b * NN * RR);
    int t = threadIdx.x;
    int lid = t & 31, wid = t >> 5;

    if (t < 16) ((float4*)sDp)[t] = ((const float4*)dpRow)[t];

    float vv[16];
    unsigned int kk[16];
#pragma unroll
    for (int i = 0; i < 4; i++) {
        float4 v = *(const float4*)&sr[t * 4 + i * 1024];
        vv[i * 4 + 0] = v.x; vv[i * 4 + 1] = v.y; vv[i * 4 + 2] = v.z; vv[i * 4 + 3] = v.w;
    }
#pragma unroll
    for (int e = 0; e < 16; e++) kk[e] = __float_as_uint(vv[e]) & 0x7fffffffu;

    unsigned int m1 = 0u, m2 = 0u;
#pragma unroll
    for (int e = 0; e < 16; e++) {
        unsigned int k = kk[e];
        if (k > m1) { m2 = m1; m1 = k; }
        else if (k > m2) { m2 = k; }
    }
#pragma unroll
    for (int o = 16; o > 0; o >>= 1) {
        unsigned int o1 = __shfl_xor_sync(0xffffffffu, m1, o);
        unsigned int o2 = __shfl_xor_sync(0xffffffffu, m2, o);
        if (o1 > m1) { m2 = (m1 > o2) ? m1 : o2; m1 = o1; }
        else { m2 = (m2 > o1) ? m2 : o1; }
    }
    if (lid == 0) warp2[wid] = m2;
    if (t == 0) sCnt = 0;
    __syncthreads();
    unsigned int T = warp2[0];
#pragma unroll
    for (int u = 1; u < 8; u++) T = (warp2[u] < T) ? warp2[u] : T;
    // widen threshold by 2% relative margin (>> split-bf16 approx error)
    unsigned int Tm = __float_as_uint(__uint_as_float(T) * 0.98f);

#pragma unroll
    for (int e = 0; e < 16; e++) {
        if (kk[e] >= Tm) {
            int p = atomicAdd(&sCnt, 1);
            if (p < 256) sColA[p] = t * 4 + (e & 3) + (e >> 2) * 1024;
        }
    }
    __syncthreads();
    int C = sCnt;
    if (C <= 256) {
        if (t < C) {
            int ci = sColA[t];
            float ex = dot64((const float4*)sDp, spb + (size_t)ci * RR);
            sVal[t] = __float_as_uint(ex);
        }
        __syncthreads();
        if (t < C) {
            unsigned int vb = sVal[t];
            unsigned int ki = vb & 0x7fffffffu;
            int ci = sColA[t];
            int rank = 0;
            for (int j = 0; j < C; j++) {
                unsigned int kj = sVal[j] & 0x7fffffffu;
                int cj = sColA[j];
                rank += (kj > ki) || (kj == ki && cj < ci);
            }
            if (rank < KK) {
                wOut[row * KK + rank] = __uint_as_float(vb);
                idxOut[row * KK + rank] = ci;
            }
        }
    } else {
        // fallback: exact re-score of the whole row, serial selection (rare)
#pragma unroll
        for (int i = 0; i < 16; i++) {
            int c = t + i * 256;
            sEx[c] = dot64((const float4*)sDp, spb + (size_t)c * RR);
        }
        __syncthreads();
        if (t == 0) {
            unsigned int bk[16]; float bv[16]; int bc[16];
            int cnt = 0;
            for (int c = 0; c < NN; c++) {
                float val = sEx[c];
                unsigned int key = __float_as_uint(val) & 0x7fffffffu;
                if (cnt == 16 && key <= bk[15]) continue;
                int pos = (cnt < 16) ? cnt : 15;
                while (pos > 0 && bk[pos - 1] < key) {
                    bk[pos] = bk[pos - 1]; bv[pos] = bv[pos - 1]; bc[pos] = bc[pos - 1];
                    pos--;
                }
                bk[pos] = key; bv[pos] = val; bc[pos] = c;
                if (cnt < 16) cnt++;
            }
            for (int k = 0; k < KK; k++) {
                wOut[row * KK + k] = bv[k];
                idxOut[row * KK + k] = bc[k];
            }
        }
    }
}

// ---------------- fused message aggregation + optional residual layernorm ----------------
__global__ void __launch_bounds__(256) msg_kernel(const float* __restrict__ w,
                                                  const int* __restrict__ idx,
                                                  const float* __restrict__ srcval, int srcB,
                                                  const float* __restrict__ state,
                                                  const float* __restrict__ res, int resMod,
                                                  const float* __restrict__ g,
                                                  const float* __restrict__ bt,
                                                  float* __restrict__ outVal,
                                                  float* __restrict__ dstate) {
    __shared__ float sW[16];
    __shared__ int sI[16];
    __shared__ float sNorm[16];
    size_t row = blockIdx.x;
    int b = (int)(row >> 12);
    int t = threadIdx.x;
    if (t < 16) { sW[t] = w[row * KK + t]; sI[t] = idx[row * KK + t]; }
    __syncthreads();
    if (t == 0) {
        float mx = 0.f;
        for (int k = 0; k < 16; k++) mx = fmaxf(mx, fabsf(sW[k]));
        float e[16];
        float s = 0.f;
        for (int k = 0; k < 16; k++) { e[k] = expf(fabsf(sW[k]) - mx); s += e[k]; }
        float inv = 1.f / s;
        float dsum = 0.f;
        for (int k = 0; k < 16; k++) {
            float u = sW[k];
            float sg = (u > 0.f) ? 1.f : ((u < 0.f) ? -1.f : 0.f);
            float wt = sg * e[k] * inv;
            if (state) {
                float st = state[(size_t)b * NN + sI[k]];
                float sp = fmaxf(st, 0.f) + log1pf(expf(-fabsf(st)));  // softplus
                wt *= sp;
            }
            sW[k] = wt;
            dsum += wt;
        }
        dstate[row] = dsum;
    }
    __syncthreads();
    const float* base = srcval + (srcB ? 0 : (size_t)b * NN * DD);
    int wid = t >> 5, lid = t & 31;
    for (int k = wid; k < 16; k += 8) {
        const float* v = base + (size_t)sI[k] * DD;
        float ss = 0.f;
#pragma unroll
        for (int i = lid; i < 256; i += 32) { float x = v[i]; ss += x * x; }
        ss = warpSum(ss);
        if (lid == 0) sNorm[k] = sqrtf(ss) + 1e-6f;
    }
    __syncthreads();
    float acc = 0.f;
#pragma unroll
    for (int k = 0; k < 16; k++) {
        const float* v = base + (size_t)sI[k] * DD;
        acc = fmaf(sW[k] / sNorm[k], v[t], acc);
    }
    if (g) {
        int srow = resMod ? (int)(row & (resMod - 1)) : (int)row;
        float v = res[(size_t)srow * DD + t] + acc;
        float mean = blockSum256(v) * (1.f / DD);
        float d = v - mean;
        float var = blockSum256(d * d) * (1.f / DD);
        outVal[row * (size_t)DD + t] = d * rsqrtf(var + 1e-5f) * g[t] + bt[t];
    } else {
        outVal[row * (size_t)DD + t] = acc;
    }
}

// ---------------- host orchestration ----------------
extern "C" void kernel_launch(void* const* d_in, const int* in_sizes, int n_in,
                              void* d_out, int out_size) {
    const float* b_state    = (const float*)d_in[0];
    const float* b_val      = (const float*)d_in[1];
    const float* init_state = (const float*)d_in[2];
    const float* init_val   = (const float*)d_in[3];
    const float* U_bk = (const float*)d_in[4];
    const float* V_bk = (const float*)d_in[5];
    const float* U_kb = (const float*)d_in[6];
    const float* V_kb = (const float*)d_in[7];
    const float* U_p  = (const float*)d_in[8];
    const float* V_p  = (const float*)d_in[9];
    const float* kn_g = (const float*)d_in[10];
    const float* kn_b = (const float*)d_in[11];
    const float* bn_g = (const float*)d_in[12];
    const float* bn_b = (const float*)d_in[13];
    const float* pn_g = (const float*)d_in[14];
    const float* pn_b = (const float*)d_in[15];

    float* out = (float*)d_out;
    float* o_rstate = out;
    float* o_rval   = o_rstate + (size_t)BB * NN;
    float* o_pstate = o_rval + (size_t)BB * NN * DD;
    float* o_pval   = o_pstate + (size_t)BB * NN;
    float* o_bds    = o_pval + (size_t)BB * NN * DD;
    float* o_bdv    = o_bds + (size_t)BB * NN;

    float *p_scores, *p_spf, *p_dpf, *p_w, *p_kstate, *p_kval, *p_nk, *p_nv, *p_nb, *p_ds;
    __nv_bfloat16 *p_sph, *p_spl, *p_dph, *p_dpl;
    int* p_idx;
    cudaGetSymbolAddress((void**)&p_scores, g_scores);
    cudaGetSymbolAddress((void**)&p_spf, g_spf);
    cudaGetSymbolAddress((void**)&p_dpf, g_dpf);
    cudaGetSymbolAddress((void**)&p_sph, g_sph);
    cudaGetSymbolAddress((void**)&p_spl, g_spl);
    cudaGetSymbolAddress((void**)&p_dph, g_dph);
    cudaGetSymbolAddress((void**)&p_dpl, g_dpl);
    cudaGetSymbolAddress((void**)&p_w, g_w);
    cudaGetSymbolAddress((void**)&p_idx, g_idx);
    cudaGetSymbolAddress((void**)&p_kstate, g_kstate);
    cudaGetSymbolAddress((void**)&p_kval, g_kval);
    cudaGetSymbolAddress((void**)&p_nk, g_nk);
    cudaGetSymbolAddress((void**)&p_nv, g_nv);
    cudaGetSymbolAddress((void**)&p_nb, g_nb);
    cudaGetSymbolAddress((void**)&p_ds, g_ds);

    cudaFuncSetAttribute(wmma_score_kernel,
                         cudaFuncAttributeMaxDynamicSharedMemorySize, WSM_TOTAL);

    dim3 mmaGrid(NN / 128, BB);

    // --- init ---
    ss_kernel<<<1, 256>>>(init_state, 1, nullptr, p_kstate);
    ln_kernel<<<NN, 256>>>(init_val, 0, nullptr, kn_g, kn_b, p_kval);
    ln_kernel<<<NN, 256>>>(p_kval, 0, nullptr, kn_g, kn_b, p_nk);

    // --- transition 1: B -> K ---
    proj_kernel<<<(BB * NN * 16) / 256, 256>>>(b_val, U_bk, p_spf, p_sph, p_spl, BB * NN);
    proj_kernel<<<(NN * 16) / 256, 256>>>(p_nk, V_bk, p_dpf, p_dph, p_dpl, NN);
    wmma_score_kernel<<<mmaGrid, 256, WSM_TOTAL>>>(p_dph, p_dpl, p_sph, p_spl, p_scores, 1, 0);
    topk_kernel<<<BB * NN, 256>>>(p_scores, p_dpf, p_spf, 1, 0, p_w, p_idx);
    msg_kernel<<<BB * NN, 256>>>(p_w, p_idx, b_val, 0, b_state,
                                 p_kval, NN, kn_g, kn_b, o_rval, p_ds);
    ss_kernel<<<BB, 256>>>(p_kstate, 1, p_ds, o_rstate);

    // --- propagation ---
    ln_kernel<<<BB * NN, 256>>>(o_rval, 0, nullptr, pn_g, pn_b, p_nv);
    proj_kernel<<<(BB * NN * 16) / 256, 256>>>(p_nv, U_p, p_spf, p_sph, p_spl, BB * NN);
    proj_kernel<<<(BB * NN * 16) / 256, 256>>>(p_nv, V_p, p_dpf, p_dph, p_dpl, BB * NN);
    wmma_score_kernel<<<mmaGrid, 256, WSM_TOTAL>>>(p_dph, p_dpl, p_sph, p_spl, p_scores, 0, 0);
    topk_kernel<<<BB * NN, 256>>>(p_scores, p_dpf, p_spf, 0, 0, p_w, p_idx);
    msg_kernel<<<BB * NN, 256>>>(p_w, p_idx, p_nv, 0, nullptr,
                                 o_rval, 0, kn_g, kn_b, o_pval, p_ds);
    ss_kernel<<<BB, 256>>>(o_rstate, 0, p_ds, o_pstate);

    // --- transition 2: K -> B (delta only) ---
    ln_kernel<<<BB * NN, 256>>>(o_pval, 0, nullptr, kn_g, kn_b, p_nv); // nk2
    ln_kernel<<<BB * NN, 256>>>(b_val, 0, nullptr, bn_g, bn_b, p_nb);  // nb
    proj_kernel<<<(BB * NN * 16) / 256, 256>>>(p_nv, U_kb, p_spf, p_sph, p_spl, BB * NN);
    proj_kernel<<<(BB * NN * 16) / 256, 256>>>(p_nb, V_kb, p_dpf, p_dph, p_dpl, BB * NN);
    wmma_score_kernel<<<mmaGrid, 256, WSM_TOTAL>>>(p_dph, p_dpl, p_sph, p_spl, p_scores, 0, 0);
    topk_kernel<<<BB * NN, 256>>>(p_scores, p_dpf, p_spf, 0, 0, p_w, p_idx);
    msg_kernel<<<BB * NN, 256>>>(p_w, p_idx, p_nv, 0, o_pstate,
                                 nullptr, 0, nullptr, nullptr, o_bdv, o_bds);
}

// round 12
// speedup vs baseline: 2.7502x; 1.0011x over previous
#include <cuda_runtime.h>
#include <cuda_bf16.h>
#include <mma.h>
#include <cstdint>
#include <cstddef>

#define BB 4
#define NN 4096
#define DD 256
#define RR 64
#define KK 16

// ---------------- device scratch (static; no runtime allocation) ----------------
__device__ __nv_bfloat16 g_scores[(size_t)BB * NN * NN];   // 128 MB (approx scores, filter only)
__device__ float g_spf[(size_t)BB * NN * RR];
__device__ float g_dpf[(size_t)BB * NN * RR];
__device__ __nv_bfloat16 g_sph[(size_t)BB * NN * RR];
__device__ __nv_bfloat16 g_spl[(size_t)BB * NN * RR];
__device__ __nv_bfloat16 g_dph[(size_t)BB * NN * RR];
__device__ __nv_bfloat16 g_dpl[(size_t)BB * NN * RR];
__device__ float g_w[(size_t)BB * NN * KK];
__device__ int   g_idx[(size_t)BB * NN * KK];
__device__ float g_kstate[NN];
__device__ float g_kval[(size_t)NN * DD];
__device__ float g_nk[(size_t)NN * DD];
__device__ float g_nv[(size_t)BB * NN * DD];
__device__ float g_nb[(size_t)BB * NN * DD];
__device__ float g_ds[(size_t)BB * NN];

// ---------------- reductions ----------------
__device__ __forceinline__ float warpSum(float v) {
#pragma unroll
    for (int o = 16; o > 0; o >>= 1) v += __shfl_xor_sync(0xffffffffu, v, o);
    return v;
}
__device__ __forceinline__ float warpMax(float v) {
#pragma unroll
    for (int o = 16; o > 0; o >>= 1) v = fmaxf(v, __shfl_xor_sync(0xffffffffu, v, o));
    return v;
}
__device__ __forceinline__ float blockSum256(float v) {
    __shared__ float sh[8];
    int wid = threadIdx.x >> 5, lid = threadIdx.x & 31;
    v = warpSum(v);
    if (lid == 0) sh[wid] = v;
    __syncthreads();
    float r = sh[0] + sh[1] + sh[2] + sh[3] + sh[4] + sh[5] + sh[6] + sh[7];
    __syncthreads();
    return r;
}
__device__ __forceinline__ float blockMax256(float v) {
    __shared__ float sh[8];
    int wid = threadIdx.x >> 5, lid = threadIdx.x & 31;
    v = warpMax(v);
    if (lid == 0) sh[wid] = v;
    __syncthreads();
    float r = fmaxf(fmaxf(fmaxf(sh[0], sh[1]), fmaxf(sh[2], sh[3])),
                    fmaxf(fmaxf(sh[4], sh[5]), fmaxf(sh[6], sh[7])));
    __syncthreads();
    return r;
}

// ---------------- layernorm over rows of 256 ----------------
__global__ void __launch_bounds__(256) ln_kernel(const float* __restrict__ x, int srcMod,
                                                 const float* __restrict__ res,
                                                 const float* __restrict__ g,
                                                 const float* __restrict__ bt,
                                                 float* __restrict__ out) {
    int row = blockIdx.x;
    int srow = srcMod ? (row & (srcMod - 1)) : row;
    int t = threadIdx.x;
    float v = x[(size_t)srow * DD + t];
    if (res) v += res[(size_t)row * DD + t];
    float mean = blockSum256(v) * (1.f / DD);
    float d = v - mean;
    float var = blockSum256(d * d) * (1.f / DD);
    out[(size_t)row * DD + t] = d * rsqrtf(var + 1e-5f) * g[t] + bt[t];
}

// ---------------- signed softmax over rows of 4096 ----------------
__global__ void __launch_bounds__(256) ss_kernel(const float* __restrict__ x, int xB,
                                                 const float* __restrict__ add,
                                                 float* __restrict__ out) {
    int b = blockIdx.x;
    const float* xr = x + (xB ? 0 : (size_t)b * NN);
    const float* ar = add ? add + (size_t)b * NN : nullptr;
    int t = threadIdx.x;
    float v[16];
    float mx = 0.f;
#pragma unroll
    for (int i = 0; i < 16; i++) {
        float u = xr[t + 256 * i];
        if (ar) u += ar[t + 256 * i];
        v[i] = u;
        mx = fmaxf(mx, fabsf(u));
    }
    mx = blockMax256(mx);
    float s = 0.f;
#pragma unroll
    for (int i = 0; i < 16; i++) s += expf(fabsf(v[i]) - mx);
    s = blockSum256(s);
    float inv = 1.f / s;
#pragma unroll
    for (int i = 0; i < 16; i++) {
        float u = v[i];
        float sg = (u > 0.f) ? 1.f : ((u < 0.f) ? -1.f : 0.f);
        out[(size_t)b * NN + t + 256 * i] = sg * expf(fabsf(u) - mx) * inv;
    }
}

// ---------------- projection: X[rows,256] @ W[256,64] -> fp32 + split bf16 (hi, lo) ----------------
__global__ void __launch_bounds__(256) proj_kernel(const float* __restrict__ X,
                                                   const float* __restrict__ W,
                                                   float* __restrict__ outF,
                                                   __nv_bfloat16* __restrict__ outH,
                                                   __nv_bfloat16* __restrict__ outL,
                                                   int nrows) {
    int gi = blockIdx.x * 256 + threadIdx.x;
    int row = gi >> 4, cq = gi & 15;
    if (row >= nrows) return;
    const float4* W4 = (const float4*)W;
    const float4* X4 = (const float4*)(X + (size_t)row * DD);
    float4 acc = make_float4(0.f, 0.f, 0.f, 0.f);
#pragma unroll 8
    for (int d4 = 0; d4 < 64; d4++) {
        float4 xv = X4[d4];
        float4 w;
        w = W4[(d4 * 4 + 0) * 16 + cq];
        acc.x = fmaf(xv.x, w.x, acc.x); acc.y = fmaf(xv.x, w.y, acc.y);
        acc.z = fmaf(xv.x, w.z, acc.z); acc.w = fmaf(xv.x, w.w, acc.w);
        w = W4[(d4 * 4 + 1) * 16 + cq];
        acc.x = fmaf(xv.y, w.x, acc.x); acc.y = fmaf(xv.y, w.y, acc.y);
        acc.z = fmaf(xv.y, w.z, acc.z); acc.w = fmaf(xv.y, w.w, acc.w);
        w = W4[(d4 * 4 + 2) * 16 + cq];
        acc.x = fmaf(xv.z, w.x, acc.x); acc.y = fmaf(xv.z, w.y, acc.y);
        acc.z = fmaf(xv.z, w.z, acc.z); acc.w = fmaf(xv.z, w.w, acc.w);
        w = W4[(d4 * 4 + 3) * 16 + cq];
        acc.x = fmaf(xv.w, w.x, acc.x); acc.y = fmaf(xv.w, w.y, acc.y);
        acc.z = fmaf(xv.w, w.z, acc.z); acc.w = fmaf(xv.w, w.w, acc.w);
    }
    ((float4*)outF)[(size_t)row * 16 + cq] = acc;
    __nv_bfloat16 hx = __float2bfloat16(acc.x);
    __nv_bfloat16 hy = __float2bfloat16(acc.y);
    __nv_bfloat16 hz = __float2bfloat16(acc.z);
    __nv_bfloat16 hw = __float2bfloat16(acc.w);
    __nv_bfloat16 lx = __float2bfloat16(acc.x - __bfloat162float(hx));
    __nv_bfloat16 ly = __float2bfloat16(acc.y - __bfloat162float(hy));
    __nv_bfloat16 lz = __float2bfloat16(acc.z - __bfloat162float(hz));
    __nv_bfloat16 lw = __float2bfloat16(acc.w - __bfloat162float(hw));
    size_t base = (size_t)row * RR + cq * 4;
    __nv_bfloat162* oh = (__nv_bfloat162*)(outH + base);
    __nv_bfloat162* ol = (__nv_bfloat162*)(outL + base);
    oh[0] = __nv_bfloat162(hx, hy); oh[1] = __nv_bfloat162(hz, hw);
    ol[0] = __nv_bfloat162(lx, ly); ol[1] = __nv_bfloat162(lz, lw);
}

// ---------------- WMMA approx score GEMM (hh + hl + lh), bf16 output ----------------
#define LDS_B 72
#define TILE_BYTES (128 * LDS_B * 2)
#define WSM_AH 0
#define WSM_AL (TILE_BYTES)
#define WSM_BH (2 * TILE_BYTES)
#define WSM_BL (3 * TILE_BYTES)
#define WSM_STAGE (4 * TILE_BYTES)          // fp32 staging: 128 x 136
#define LDS_S 136
#define WSM_TOTAL (WSM_STAGE + 128 * LDS_S * 4)

using namespace nvcuda;

__global__ void __launch_bounds__(256) wmma_score_kernel(const __nv_bfloat16* __restrict__ dph,
                                                         const __nv_bfloat16* __restrict__ dpl,
                                                         const __nv_bfloat16* __restrict__ sph,
                                                         const __nv_bfloat16* __restrict__ spl,
                                                         __nv_bfloat16* __restrict__ out,
                                                         int dpB, int spB) {
    extern __shared__ char smemRaw[];
    __nv_bfloat16* sAh = (__nv_bfloat16*)(smemRaw + WSM_AH);
    __nv_bfloat16* sAl = (__nv_bfloat16*)(smemRaw + WSM_AL);
    __nv_bfloat16* sBh = (__nv_bfloat16*)(smemRaw + WSM_BH);
    __nv_bfloat16* sBl = (__nv_bfloat16*)(smemRaw + WSM_BL);
    float* sStage = (float*)(smemRaw + WSM_STAGE);

    int t = threadIdx.x;
    int w = t >> 5;
    int wn = w >> 1;
    int wm = w & 1;
    int n0 = blockIdx.x * 128;
    int b = blockIdx.y;
    const __nv_bfloat16* dphb = dph + (dpB ? 0 : (size_t)b * NN * RR);
    const __nv_bfloat16* dplb = dpl + (dpB ? 0 : (size_t)b * NN * RR);
    const __nv_bfloat16* sphb = sph + (spB ? 0 : (size_t)b * NN * RR);
    const __nv_bfloat16* splb = spl + (spB ? 0 : (size_t)b * NN * RR);

#pragma unroll
    for (int i = 0; i < 4; i++) {
        int s = t + i * 256;
        int r = s >> 3, q = s & 7;
        *(float4*)&sAh[r * LDS_B + q * 8] = *(const float4*)(dphb + (size_t)(n0 + r) * RR + q * 8);
        *(float4*)&sAl[r * LDS_B + q * 8] = *(const float4*)(dplb + (size_t)(n0 + r) * RR + q * 8);
    }

    for (int mt = 0; mt < 32; mt++) {
        int m0 = mt * 128;
        __syncthreads();   // prev staging reads + prev B use complete
#pragma unroll
        for (int i = 0; i < 4; i++) {
            int s = t + i * 256;
            int r = s >> 3, q = s & 7;
            *(float4*)&sBh[r * LDS_B + q * 8] = *(const float4*)(sphb + (size_t)(m0 + r) * RR + q * 8);
            *(float4*)&sBl[r * LDS_B + q * 8] = *(const float4*)(splb + (size_t)(m0 + r) * RR + q * 8);
        }
        __syncthreads();

        wmma::fragment<wmma::accumulator, 16, 16, 16, float> acc[2][4];
#pragma unroll
        for (int i = 0; i < 2; i++)
#pragma unroll
            for (int j = 0; j < 4; j++) wmma::fill_fragment(acc[i][j], 0.f);

#pragma unroll
        for (int ks = 0; ks < 4; ks++) {
            wmma::fragment<wmma::matrix_a, 16, 16, 16, __nv_bfloat16, wmma::row_major> ah0, ah1, al0, al1;
            wmma::load_matrix_sync(ah0, &sAh[(wn * 32 + 0) * LDS_B + ks * 16], LDS_B);
            wmma::load_matrix_sync(ah1, &sAh[(wn * 32 + 16) * LDS_B + ks * 16], LDS_B);
            wmma::load_matrix_sync(al0, &sAl[(wn * 32 + 0) * LDS_B + ks * 16], LDS_B);
            wmma::load_matrix_sync(al1, &sAl[(wn * 32 + 16) * LDS_B + ks * 16], LDS_B);
#pragma unroll
            for (int j = 0; j < 4; j++) {
                wmma::fragment<wmma::matrix_b, 16, 16, 16, __nv_bfloat16, wmma::col_major> bh, bl;
                wmma::load_matrix_sync(bh, &sBh[(wm * 64 + j * 16) * LDS_B + ks * 16], LDS_B);
                wmma::load_matrix_sync(bl, &sBl[(wm * 64 + j * 16) * LDS_B + ks * 16], LDS_B);
                wmma::mma_sync(acc[0][j], ah0, bh, acc[0][j]);
                wmma::mma_sync(acc[1][j], ah1, bh, acc[1][j]);
                wmma::mma_sync(acc[0][j], ah0, bl, acc[0][j]);
                wmma::mma_sync(acc[1][j], ah1, bl, acc[1][j]);
                wmma::mma_sync(acc[0][j], al0, bh, acc[0][j]);
                wmma::mma_sync(acc[1][j], al1, bh, acc[1][j]);
            }
        }

        // stage fp32 tile in smem, convert to bf16, write coalesced
#pragma unroll
        for (int i = 0; i < 2; i++)
#pragma unroll
            for (int j = 0; j < 4; j++) {
#pragma unroll
                for (int e = 0; e < acc[i][j].num_elements; e++) acc[i][j].x[e] *= 0.125f;
                wmma::store_matrix_sync(&sStage[(wn * 32 + i * 16) * LDS_S + wm * 64 + j * 16],
                                        acc[i][j], LDS_S, wmma::mem_row_major);
            }
        __syncthreads();
#pragma unroll
        for (int p = 0; p < 8; p++) {
            int id = t + p * 256;        // 0..2047
            int r = id >> 4;             // row 0..127
            int cg = id & 15;            // 8-col group
            const float* sp8 = &sStage[r * LDS_S + cg * 8];
            float4 v0 = *(const float4*)sp8;
            float4 v1 = *(const float4*)(sp8 + 4);
            __nv_bfloat162 o0 = __nv_bfloat162(__float2bfloat16(v0.x), __float2bfloat16(v0.y));
            __nv_bfloat162 o1 = __nv_bfloat162(__float2bfloat16(v0.z), __float2bfloat16(v0.w));
            __nv_bfloat162 o2 = __nv_bfloat162(__float2bfloat16(v1.x), __float2bfloat16(v1.y));
            __nv_bfloat162 o3 = __nv_bfloat162(__float2bfloat16(v1.z), __float2bfloat16(v1.w));
            uint4 pk;
            pk.x = *(unsigned int*)&o0; pk.y = *(unsigned int*)&o1;
            pk.z = *(unsigned int*)&o2; pk.w = *(unsigned int*)&o3;
            *(uint4*)(out + ((size_t)b * NN + n0 + r) * NN + m0 + cg * 8) = pk;
        }
    }
}

// ---------------- top-16: bf16 approx filter (2% margin) + EXACT fp32 re-score ----------------
__device__ __forceinline__ float dot64(const float4* a4, const float* bp) {
    const float4* b4 = (const float4*)bp;
    float s = 0.f;
#pragma unroll
    for (int q = 0; q < 16; q++) {
        float4 a = a4[q], b = b4[q];
        s = fmaf(a.x, b.x, s); s = fmaf(a.y, b.y, s);
        s = fmaf(a.z, b.z, s); s = fmaf(a.w, b.w, s);
    }
    return s * 0.125f;
}

__global__ void __launch_bounds__(256) topk_kernel(const __nv_bfloat16* __restrict__ approx,
                                                   const float* __restrict__ dpf,
                                                   const float* __restrict__ spf,
                                                   int dpB, int spB,
                                                   float* __restrict__ wOut,
                                                   int* __restrict__ idxOut) {
    __shared__ float sEx[4096];          // fallback exact row (rarely used)
    __shared__ float sDp[64];
    __shared__ unsigned int sVal[256];
    __shared__ int sColA[256];
    __shared__ unsigned int warp2[8];
    __shared__ int sCnt;
    size_t row = blockIdx.x;
    int b = (int)(row >> 12);
    int n = (int)(row & (NN - 1));
    const __nv_bfloat16* sr = approx + row * (size_t)NN;
    const float* dpRow = dpf + (dpB ? 0 : (size_t)b * NN * RR) + (size_t)n * RR;
    const float* spb = spf + (spB ? 0 : (size_t)b * NN * RR);
    int t = threadIdx.x;
    int lid = t & 31, wid = t >> 5;

    if (t < 16) ((float4*)sDp)[t] = ((const float4*)dpRow)[t];

    // 16 bf16 scores per thread: two uint4 loads of 8 bf16 each
    unsigned int kk[16];
#pragma unroll
    for (int i = 0; i < 2; i++) {
        uint4 v = ((const uint4*)sr)[t + i * 256];
        unsigned int ws[4] = {v.x, v.y, v.z, v.w};
#pragma unroll
        for (int h = 0; h < 4; h++) {
            kk[i * 8 + h * 2 + 0] = (ws[h] << 16) & 0x7fffffffu;   // low bf16 -> fp32 bits, abs
            kk[i * 8 + h * 2 + 1] = ws[h] & 0x7fff0000u;           // high bf16 -> fp32 bits, abs
        }
    }

    unsigned int m1 = 0u, m2 = 0u;
#pragma unroll
    for (int e = 0; e < 16; e++) {
        unsigned int k = kk[e];
        if (k > m1) { m2 = m1; m1 = k; }
        else if (k > m2) { m2 = k; }
    }
#pragma unroll
    for (int o = 16; o > 0; o >>= 1) {
        unsigned int o1 = __shfl_xor_sync(0xffffffffu, m1, o);
        unsigned int o2 = __shfl_xor_sync(0xffffffffu, m2, o);
        if (o1 > m1) { m2 = (m1 > o2) ? m1 : o2; m1 = o1; }
        else { m2 = (m2 > o1) ? m2 : o1; }
    }
    if (lid == 0) warp2[wid] = m2;
    if (t == 0) sCnt = 0;
    __syncthreads();
    unsigned int T = warp2[0];
#pragma unroll
    for (int u = 1; u < 8; u++) T = (warp2[u] < T) ? warp2[u] : T;
    // widen threshold by 2% relative margin (>> split-bf16 + bf16-storage error)
    unsigned int Tm = __float_as_uint(__uint_as_float(T) * 0.98f);

#pragma unroll
    for (int e = 0; e < 16; e++) {
        if (kk[e] >= Tm) {
            int p = atomicAdd(&sCnt, 1);
            if (p < 256) sColA[p] = (t + (e >> 3) * 256) * 8 + (e & 7);
        }
    }
    __syncthreads();
    int C = sCnt;
    if (C <= 256) {
        if (t < C) {
            int ci = sColA[t];
            float ex = dot64((const float4*)sDp, spb + (size_t)ci * RR);
            sVal[t] = __float_as_uint(ex);
        }
        __syncthreads();
        if (t < C) {
            unsigned int vb = sVal[t];
            unsigned int ki = vb & 0x7fffffffu;
            int ci = sColA[t];
            int rank = 0;
            for (int j = 0; j < C; j++) {
                unsigned int kj = sVal[j] & 0x7fffffffu;
                int cj = sColA[j];
                rank += (kj > ki) || (kj == ki && cj < ci);
            }
            if (rank < KK) {
                wOut[row * KK + rank] = __uint_as_float(vb);
                idxOut[row * KK + rank] = ci;
            }
        }
    } else {
        // fallback: exact re-score of the whole row, serial selection (rare)
#pragma unroll
        for (int i = 0; i < 16; i++) {
            int c = t + i * 256;
            sEx[c] = dot64((const float4*)sDp, spb + (size_t)c * RR);
        }
        __syncthreads();
        if (t == 0) {
            unsigned int bk[16]; float bv[16]; int bc[16];
            int cnt = 0;
            for (int c = 0; c < NN; c++) {
                float val = sEx[c];
                unsigned int key = __float_as_uint(val) & 0x7fffffffu;
                if (cnt == 16 && key <= bk[15]) continue;
                int pos = (cnt < 16) ? cnt : 15;
                while (pos > 0 && bk[pos - 1] < key) {
                    bk[pos] = bk[pos - 1]; bv[pos] = bv[pos - 1]; bc[pos] = bc[pos - 1];
                    pos--;
                }
                bk[pos] = key; bv[pos] = val; bc[pos] = c;
                if (cnt < 16) cnt++;
            }
            for (int k = 0; k < KK; k++) {
                wOut[row * KK + k] = bv[k];
                idxOut[row * KK + k] = bc[k];
            }
        }
    }
}

// ---------------- fused message aggregation + optional residual layernorm ----------------
__global__ void __launch_bounds__(256) msg_kernel(const float* __restrict__ w,
                                                  const int* __restrict__ idx,
                                                  const float* __restrict__ srcval, int srcB,
                                                  const float* __restrict__ state,
                                                  const float* __restrict__ res, int resMod,
                                                  const float* __restrict__ g,
                                                  const float* __restrict__ bt,
                                                  float* __restrict__ outVal,
                                                  float* __restrict__ dstate) {
    __shared__ float sW[16];
    __shared__ int sI[16];
    __shared__ float sNorm[16];
    size_t row = blockIdx.x;
    int b = (int)(row >> 12);
    int t = threadIdx.x;
    if (t < 16) { sW[t] = w[row * KK + t]; sI[t] = idx[row * KK + t]; }
    __syncthreads();
    if (t == 0) {
        float mx = 0.f;
        for (int k = 0; k < 16; k++) mx = fmaxf(mx, fabsf(sW[k]));
        float e[16];
        float s = 0.f;
        for (int k = 0; k < 16; k++) { e[k] = expf(fabsf(sW[k]) - mx); s += e[k]; }
        float inv = 1.f / s;
        float dsum = 0.f;
        for (int k = 0; k < 16; k++) {
            float u = sW[k];
            float sg = (u > 0.f) ? 1.f : ((u < 0.f) ? -1.f : 0.f);
            float wt = sg * e[k] * inv;
            if (state) {
                float st = state[(size_t)b * NN + sI[k]];
                float sp = fmaxf(st, 0.f) + log1pf(expf(-fabsf(st)));  // softplus
                wt *= sp;
            }
            sW[k] = wt;
            dsum += wt;
        }
        dstate[row] = dsum;
    }
    __syncthreads();
    const float* base = srcval + (srcB ? 0 : (size_t)b * NN * DD);
    int wid = t >> 5, lid = t & 31;
    for (int k = wid; k < 16; k += 8) {
        const float* v = base + (size_t)sI[k] * DD;
        float ss = 0.f;
#pragma unroll
        for (int i = lid; i < 256; i += 32) { float x = v[i]; ss += x * x; }
        ss = warpSum(ss);
        if (lid == 0) sNorm[k] = sqrtf(ss) + 1e-6f;
    }
    __syncthreads();
    float acc = 0.f;
#pragma unroll
    for (int k = 0; k < 16; k++) {
        const float* v = base + (size_t)sI[k] * DD;
        acc = fmaf(sW[k] / sNorm[k], v[t], acc);
    }
    if (g) {
        int srow = resMod ? (int)(row & (resMod - 1)) : (int)row;
        float v = res[(size_t)srow * DD + t] + acc;
        float mean = blockSum256(v) * (1.f / DD);
        float d = v - mean;
        float var = blockSum256(d * d) * (1.f / DD);
        outVal[row * (size_t)DD + t] = d * rsqrtf(var + 1e-5f) * g[t] + bt[t];
    } else {
        outVal[row * (size_t)DD + t] = acc;
    }
}

// ---------------- host orchestration ----------------
extern "C" void kernel_launch(void* const* d_in, const int* in_sizes, int n_in,
                              void* d_out, int out_size) {
    const float* b_state    = (const float*)d_in[0];
    const float* b_val      = (const float*)d_in[1];
    const float* init_state = (const float*)d_in[2];
    const float* init_val   = (const float*)d_in[3];
    const float* U_bk = (const float*)d_in[4];
    const float* V_bk = (const float*)d_in[5];
    const float* U_kb = (const float*)d_in[6];
    const float* V_kb = (const float*)d_in[7];
    const float* U_p  = (const float*)d_in[8];
    const float* V_p  = (const float*)d_in[9];
    const float* kn_g = (const float*)d_in[10];
    const float* kn_b = (const float*)d_in[11];
    const float* bn_g = (const float*)d_in[12];
    const float* bn_b = (const float*)d_in[13];
    const float* pn_g = (const float*)d_in[14];
    const float* pn_b = (const float*)d_in[15];

    float* out = (float*)d_out;
    float* o_rstate = out;
    float* o_rval   = o_rstate + (size_t)BB * NN;
    float* o_pstate = o_rval + (size_t)BB * NN * DD;
    float* o_pval   = o_pstate + (size_t)BB * NN;
    float* o_bds    = o_pval + (size_t)BB * NN * DD;
    float* o_bdv    = o_bds + (size_t)BB * NN;

    float *p_spf, *p_dpf, *p_w, *p_kstate, *p_kval, *p_nk, *p_nv, *p_nb, *p_ds;
    __nv_bfloat16 *p_scores, *p_sph, *p_spl, *p_dph, *p_dpl;
    int* p_idx;
    cudaGetSymbolAddress((void**)&p_scores, g_scores);
    cudaGetSymbolAddress((void**)&p_spf, g_spf);
    cudaGetSymbolAddress((void**)&p_dpf, g_dpf);
    cudaGetSymbolAddress((void**)&p_sph, g_sph);
    cudaGetSymbolAddress((void**)&p_spl, g_spl);
    cudaGetSymbolAddress((void**)&p_dph, g_dph);
    cudaGetSymbolAddress((void**)&p_dpl, g_dpl);
    cudaGetSymbolAddress((void**)&p_w, g_w);
    cudaGetSymbolAddress((void**)&p_idx, g_idx);
    cudaGetSymbolAddress((void**)&p_kstate, g_kstate);
    cudaGetSymbolAddress((void**)&p_kval, g_kval);
    cudaGetSymbolAddress((void**)&p_nk, g_nk);
    cudaGetSymbolAddress((void**)&p_nv, g_nv);
    cudaGetSymbolAddress((void**)&p_nb, g_nb);
    cudaGetSymbolAddress((void**)&p_ds, g_ds);

    cudaFuncSetAttribute(wmma_score_kernel,
                         cudaFuncAttributeMaxDynamicSharedMemorySize, WSM_TOTAL);

    dim3 mmaGrid(NN / 128, BB);

    // --- init ---
    ss_kernel<<<1, 256>>>(init_state, 1, nullptr, p_kstate);
    ln_kernel<<<NN, 256>>>(init_val, 0, nullptr, kn_g, kn_b, p_kval);
    ln_kernel<<<NN, 256>>>(p_kval, 0, nullptr, kn_g, kn_b, p_nk);

    // --- transition 1: B -> K ---
    proj_kernel<<<(BB * NN * 16) / 256, 256>>>(b_val, U_bk, p_spf, p_sph, p_spl, BB * NN);
    proj_kernel<<<(NN * 16) / 256, 256>>>(p_nk, V_bk, p_dpf, p_dph, p_dpl, NN);
    wmma_score_kernel<<<mmaGrid, 256, WSM_TOTAL>>>(p_dph, p_dpl, p_sph, p_spl, p_scores, 1, 0);
    topk_kernel<<<BB * NN, 256>>>(p_scores, p_dpf, p_spf, 1, 0, p_w, p_idx);
    msg_kernel<<<BB * NN, 256>>>(p_w, p_idx, b_val, 0, b_state,
                                 p_kval, NN, kn_g, kn_b, o_rval, p_ds);
    ss_kernel<<<BB, 256>>>(p_kstate, 1, p_ds, o_rstate);

    // --- propagation ---
    ln_kernel<<<BB * NN, 256>>>(o_rval, 0, nullptr, pn_g, pn_b, p_nv);
    proj_kernel<<<(BB * NN * 16) / 256, 256>>>(p_nv, U_p, p_spf, p_sph, p_spl, BB * NN);
    proj_kernel<<<(BB * NN * 16) / 256, 256>>>(p_nv, V_p, p_dpf, p_dph, p_dpl, BB * NN);
    wmma_score_kernel<<<mmaGrid, 256, WSM_TOTAL>>>(p_dph, p_dpl, p_sph, p_spl, p_scores, 0, 0);
    topk_kernel<<<BB * NN, 256>>>(p_scores, p_dpf, p_spf, 0, 0, p_w, p_idx);
    msg_kernel<<<BB * NN, 256>>>(p_w, p_idx, p_nv, 0, nullptr,
                                 o_rval, 0, kn_g, kn_b, o_pval, p_ds);
    ss_kernel<<<BB, 256>>>(o_rstate, 0, p_ds, o_pstate);

    // --- transition 2: K -> B (delta only) ---
    ln_kernel<<<BB * NN, 256>>>(o_pval, 0, nullptr, kn_g, kn_b, p_nv); // nk2
    ln_kernel<<<BB * NN, 256>>>(b_val, 0, nullptr, bn_g, bn_b, p_nb);  // nb
    proj_kernel<<<(BB * NN * 16) / 256, 256>>>(p_nv, U_kb, p_spf, p_sph, p_spl, BB * NN);
    proj_kernel<<<(BB * NN * 16) / 256, 256>>>(p_nb, V_kb, p_dpf, p_dph, p_dpl, BB * NN);
    wmma_score_kernel<<<mmaGrid, 256, WSM_TOTAL>>>(p_dph, p_dpl, p_sph, p_spl, p_scores, 0, 0);
    topk_kernel<<<BB * NN, 256>>>(p_scores, p_dpf, p_spf, 0, 0, p_w, p_idx);
    msg_kernel<<<BB * NN, 256>>>(p_w, p_idx, p_nv, 0, o_pstate,
                                 nullptr, 0, nullptr, nullptr, o_bdv, o_bds);
}

// round 13
// speedup vs baseline: 2.8582x; 1.0393x over previous
#include <cuda_runtime.h>
#include <cuda_bf16.h>
#include <mma.h>
#include <cstdint>
#include <cstddef>

#define BB 4
#define NN 4096
#define DD 256
#define RR 64
#define KK 16

// ---------------- device scratch (static; no runtime allocation) ----------------
__device__ float g_scores[(size_t)BB * NN * NN];     // 256 MB (approx scores, filter only)
__device__ float g_spf[(size_t)BB * NN * RR];
__device__ float g_dpf[(size_t)BB * NN * RR];
__device__ __nv_bfloat16 g_sph[(size_t)BB * NN * RR];
__device__ __nv_bfloat16 g_dph[(size_t)BB * NN * RR];
__device__ float g_w[(size_t)BB * NN * KK];
__device__ int   g_idx[(size_t)BB * NN * KK];
__device__ float g_kstate[NN];
__device__ float g_kval[(size_t)NN * DD];
__device__ float g_nk[(size_t)NN * DD];
__device__ float g_nv[(size_t)BB * NN * DD];
__device__ float g_nb[(size_t)BB * NN * DD];
__device__ float g_ds[(size_t)BB * NN];

// ---------------- reductions ----------------
__device__ __forceinline__ float warpSum(float v) {
#pragma unroll
    for (int o = 16; o > 0; o >>= 1) v += __shfl_xor_sync(0xffffffffu, v, o);
    return v;
}
__device__ __forceinline__ float warpMax(float v) {
#pragma unroll
    for (int o = 16; o > 0; o >>= 1) v = fmaxf(v, __shfl_xor_sync(0xffffffffu, v, o));
    return v;
}
__device__ __forceinline__ float blockSum256(float v) {
    __shared__ float sh[8];
    int wid = threadIdx.x >> 5, lid = threadIdx.x & 31;
    v = warpSum(v);
    if (lid == 0) sh[wid] = v;
    __syncthreads();
    float r = sh[0] + sh[1] + sh[2] + sh[3] + sh[4] + sh[5] + sh[6] + sh[7];
    __syncthreads();
    return r;
}
__device__ __forceinline__ float blockMax256(float v) {
    __shared__ float sh[8];
    int wid = threadIdx.x >> 5, lid = threadIdx.x & 31;
    v = warpMax(v);
    if (lid == 0) sh[wid] = v;
    __syncthreads();
    float r = fmaxf(fmaxf(fmaxf(sh[0], sh[1]), fmaxf(sh[2], sh[3])),
                    fmaxf(fmaxf(sh[4], sh[5]), fmaxf(sh[6], sh[7])));
    __syncthreads();
    return r;
}

// ---------------- layernorm over rows of 256 ----------------
__global__ void __launch_bounds__(256) ln_kernel(const float* __restrict__ x, int srcMod,
                                                 const float* __restrict__ res,
                                                 const float* __restrict__ g,
                                                 const float* __restrict__ bt,
                                                 float* __restrict__ out) {
    int row = blockIdx.x;
    int srow = srcMod ? (row & (srcMod - 1)) : row;
    int t = threadIdx.x;
    float v = x[(size_t)srow * DD + t];
    if (res) v += res[(size_t)row * DD + t];
    float mean = blockSum256(v) * (1.f / DD);
    float d = v - mean;
    float var = blockSum256(d * d) * (1.f / DD);
    out[(size_t)row * DD + t] = d * rsqrtf(var + 1e-5f) * g[t] + bt[t];
}

// ---------------- signed softmax over rows of 4096 ----------------
__global__ void __launch_bounds__(256) ss_kernel(const float* __restrict__ x, int xB,
                                                 const float* __restrict__ add,
                                                 float* __restrict__ out) {
    int b = blockIdx.x;
    const float* xr = x + (xB ? 0 : (size_t)b * NN);
    const float* ar = add ? add + (size_t)b * NN : nullptr;
    int t = threadIdx.x;
    float v[16];
    float mx = 0.f;
#pragma unroll
    for (int i = 0; i < 16; i++) {
        float u = xr[t + 256 * i];
        if (ar) u += ar[t + 256 * i];
        v[i] = u;
        mx = fmaxf(mx, fabsf(u));
    }
    mx = blockMax256(mx);
    float s = 0.f;
#pragma unroll
    for (int i = 0; i < 16; i++) s += expf(fabsf(v[i]) - mx);
    s = blockSum256(s);
    float inv = 1.f / s;
#pragma unroll
    for (int i = 0; i < 16; i++) {
        float u = v[i];
        float sg = (u > 0.f) ? 1.f : ((u < 0.f) ? -1.f : 0.f);
        out[(size_t)b * NN + t + 256 * i] = sg * expf(fabsf(u) - mx) * inv;
    }
}

// ---------------- projection: X[rows,256] @ W[256,64] -> fp32 + bf16(hi) ----------------
__global__ void __launch_bounds__(256) proj_kernel(const float* __restrict__ X,
                                                   const float* __restrict__ W,
                                                   float* __restrict__ outF,
                                                   __nv_bfloat16* __restrict__ outH,
                                                   int nrows) {
    int gi = blockIdx.x * 256 + threadIdx.x;
    int row = gi >> 4, cq = gi & 15;
    if (row >= nrows) return;
    const float4* W4 = (const float4*)W;
    const float4* X4 = (const float4*)(X + (size_t)row * DD);
    float4 acc = make_float4(0.f, 0.f, 0.f, 0.f);
#pragma unroll 8
    for (int d4 = 0; d4 < 64; d4++) {
        float4 xv = X4[d4];
        float4 w;
        w = W4[(d4 * 4 + 0) * 16 + cq];
        acc.x = fmaf(xv.x, w.x, acc.x); acc.y = fmaf(xv.x, w.y, acc.y);
        acc.z = fmaf(xv.x, w.z, acc.z); acc.w = fmaf(xv.x, w.w, acc.w);
        w = W4[(d4 * 4 + 1) * 16 + cq];
        acc.x = fmaf(xv.y, w.x, acc.x); acc.y = fmaf(xv.y, w.y, acc.y);
        acc.z = fmaf(xv.y, w.z, acc.z); acc.w = fmaf(xv.y, w.w, acc.w);
        w = W4[(d4 * 4 + 2) * 16 + cq];
        acc.x = fmaf(xv.z, w.x, acc.x); acc.y = fmaf(xv.z, w.y, acc.y);
        acc.z = fmaf(xv.z, w.z, acc.z); acc.w = fmaf(xv.z, w.w, acc.w);
        w = W4[(d4 * 4 + 3) * 16 + cq];
        acc.x = fmaf(xv.w, w.x, acc.x); acc.y = fmaf(xv.w, w.y, acc.y);
        acc.z = fmaf(xv.w, w.z, acc.z); acc.w = fmaf(xv.w, w.w, acc.w);
    }
    ((float4*)outF)[(size_t)row * 16 + cq] = acc;
    __nv_bfloat162 h0 = __nv_bfloat162(__float2bfloat16(acc.x), __float2bfloat16(acc.y));
    __nv_bfloat162 h1 = __nv_bfloat162(__float2bfloat16(acc.z), __float2bfloat16(acc.w));
    size_t base = (size_t)row * RR + cq * 4;
    __nv_bfloat162* oh = (__nv_bfloat162*)(outH + base);
    oh[0] = h0; oh[1] = h1;
}

// ---------------- WMMA approx score GEMM (hi-only), fp32 output ----------------
// CTA tile 64(n) x 128(m), grid (64, 4) = 256 CTAs, 27KB static smem -> high occupancy.
#define LDS_B 72

using namespace nvcuda;

__global__ void __launch_bounds__(256) wmma_score_kernel(const __nv_bfloat16* __restrict__ dph,
                                                         const __nv_bfloat16* __restrict__ sph,
                                                         float* __restrict__ out,
                                                         int dpB, int spB) {
    __shared__ __nv_bfloat16 sA[64 * LDS_B];    //  9216 B
    __shared__ __nv_bfloat16 sB[128 * LDS_B];   // 18432 B

    int t = threadIdx.x;
    int w = t >> 5;
    int wn = w & 1;            // 0..1 : n-subtile of 32
    int wm = w >> 1;           // 0..3 : m-subtile of 32
    int n0 = blockIdx.x * 64;
    int b = blockIdx.y;
    const __nv_bfloat16* dphb = dph + (dpB ? 0 : (size_t)b * NN * RR);
    const __nv_bfloat16* sphb = sph + (spB ? 0 : (size_t)b * NN * RR);

    // load resident A tile: 64 rows x 64 bf16 (512 float4 -> 2 per thread)
#pragma unroll
    for (int i = 0; i < 2; i++) {
        int s = t + i * 256;
        int r = s >> 3, q = s & 7;
        *(float4*)&sA[r * LDS_B + q * 8] = *(const float4*)(dphb + (size_t)(n0 + r) * RR + q * 8);
    }

    for (int mt = 0; mt < 32; mt++) {
        int m0 = mt * 128;
        __syncthreads();       // prev compute done before overwriting B
#pragma unroll
        for (int i = 0; i < 4; i++) {
            int s = t + i * 256;
            int r = s >> 3, q = s & 7;
            *(float4*)&sB[r * LDS_B + q * 8] = *(const float4*)(sphb + (size_t)(m0 + r) * RR + q * 8);
        }
        __syncthreads();

        wmma::fragment<wmma::accumulator, 16, 16, 16, float> acc[2][2];
#pragma unroll
        for (int i = 0; i < 2; i++)
#pragma unroll
            for (int j = 0; j < 2; j++) wmma::fill_fragment(acc[i][j], 0.f);

#pragma unroll
        for (int ks = 0; ks < 4; ks++) {
            wmma::fragment<wmma::matrix_a, 16, 16, 16, __nv_bfloat16, wmma::row_major> a0, a1;
            wmma::fragment<wmma::matrix_b, 16, 16, 16, __nv_bfloat16, wmma::col_major> b0, b1;
            wmma::load_matrix_sync(a0, &sA[(wn * 32 + 0) * LDS_B + ks * 16], LDS_B);
            wmma::load_matrix_sync(a1, &sA[(wn * 32 + 16) * LDS_B + ks * 16], LDS_B);
            wmma::load_matrix_sync(b0, &sB[(wm * 32 + 0) * LDS_B + ks * 16], LDS_B);
            wmma::load_matrix_sync(b1, &sB[(wm * 32 + 16) * LDS_B + ks * 16], LDS_B);
            wmma::mma_sync(acc[0][0], a0, b0, acc[0][0]);
            wmma::mma_sync(acc[0][1], a0, b1, acc[0][1]);
            wmma::mma_sync(acc[1][0], a1, b0, acc[1][0]);
            wmma::mma_sync(acc[1][1], a1, b1, acc[1][1]);
        }

#pragma unroll
        for (int i = 0; i < 2; i++)
#pragma unroll
            for (int j = 0; j < 2; j++) {
#pragma unroll
                for (int e = 0; e < acc[i][j].num_elements; e++) acc[i][j].x[e] *= 0.125f;
                float* op = out + ((size_t)b * NN + n0 + wn * 32 + i * 16) * NN
                              + m0 + wm * 32 + j * 16;
                wmma::store_matrix_sync(op, acc[i][j], NN, wmma::mem_row_major);
            }
    }
}

// ---------------- top-16: approx filter (8% margin) + EXACT fp32 re-score ----------------
__device__ __forceinline__ float dot64(const float4* a4, const float* bp) {
    const float4* b4 = (const float4*)bp;
    float s = 0.f;
#pragma unroll
    for (int q = 0; q < 16; q++) {
        float4 a = a4[q], b = b4[q];
        s = fmaf(a.x, b.x, s); s = fmaf(a.y, b.y, s);
        s = fmaf(a.z, b.z, s); s = fmaf(a.w, b.w, s);
    }
    return s * 0.125f;
}

__global__ void __launch_bounds__(256) topk_kernel(const float* __restrict__ approx,
                                                   const float* __restrict__ dpf,
                                                   const float* __restrict__ spf,
                                                   int dpB, int spB,
                                                   float* __restrict__ wOut,
                                                   int* __restrict__ idxOut) {
    __shared__ float sEx[4096];          // fallback exact row (rarely used)
    __shared__ float sDp[64];
    __shared__ unsigned int sVal[256];
    __shared__ int sColA[256];
    __shared__ unsigned int warp2[8];
    __shared__ int sCnt;
    size_t row = blockIdx.x;
    int b = (int)(row >> 12);
    int n = (int)(row & (NN - 1));
    const float* sr = approx + row * (size_t)NN;
    const float* dpRow = dpf + (dpB ? 0 : (size_t)b * NN * RR) + (size_t)n * RR;
    const float* spb = spf + (spB ? 0 : (size_t)b * NN * RR);
    int t = threadIdx.x;
    int lid = t & 31, wid = t >> 5;

    if (t < 16) ((float4*)sDp)[t] = ((const float4*)dpRow)[t];

    float vv[16];
    unsigned int kk[16];
#pragma unroll
    for (int i = 0; i < 4; i++) {
        float4 v = *(const float4*)&sr[t * 4 + i * 1024];
        vv[i * 4 + 0] = v.x; vv[i * 4 + 1] = v.y; vv[i * 4 + 2] = v.z; vv[i * 4 + 3] = v.w;
    }
#pragma unroll
    for (int e = 0; e < 16; e++) kk[e] = __float_as_uint(vv[e]) & 0x7fffffffu;

    unsigned int m1 = 0u, m2 = 0u;
#pragma unroll
    for (int e = 0; e < 16; e++) {
        unsigned int k = kk[e];
        if (k > m1) { m2 = m1; m1 = k; }
        else if (k > m2) { m2 = k; }
    }
#pragma unroll
    for (int o = 16; o > 0; o >>= 1) {
        unsigned int o1 = __shfl_xor_sync(0xffffffffu, m1, o);
        unsigned int o2 = __shfl_xor_sync(0xffffffffu, m2, o);
        if (o1 > m1) { m2 = (m1 > o2) ? m1 : o2; m1 = o1; }
        else { m2 = (m2 > o1) ? m2 : o1; }
    }
    if (lid == 0) warp2[wid] = m2;
    if (t == 0) sCnt = 0;
    __syncthreads();
    unsigned int T = warp2[0];
#pragma unroll
    for (int u = 1; u < 8; u++) T = (warp2[u] < T) ? warp2[u] : T;
    // widen threshold by 8% relative margin (~50 sigma of hi-only bf16 filter error)
    unsigned int Tm = __float_as_uint(__uint_as_float(T) * 0.92f);

#pragma unroll
    for (int e = 0; e < 16; e++) {
        if (kk[e] >= Tm) {
            int p = atomicAdd(&sCnt, 1);
            if (p < 256) sColA[p] = t * 4 + (e & 3) + (e >> 2) * 1024;
        }
    }
    __syncthreads();
    int C = sCnt;
    if (C <= 256) {
        if (t < C) {
            int ci = sColA[t];
            float ex = dot64((const float4*)sDp, spb + (size_t)ci * RR);
            sVal[t] = __float_as_uint(ex);
        }
        __syncthreads();
        if (t < C) {
            unsigned int vb = sVal[t];
            unsigned int ki = vb & 0x7fffffffu;
            int ci = sColA[t];
            int rank = 0;
            for (int j = 0; j < C; j++) {
                unsigned int kj = sVal[j] & 0x7fffffffu;
                int cj = sColA[j];
                rank += (kj > ki) || (kj == ki && cj < ci);
            }
            if (rank < KK) {
                wOut[row * KK + rank] = __uint_as_float(vb);
                idxOut[row * KK + rank] = ci;
            }
        }
    } else {
        // fallback: exact re-score of the whole row, serial selection (rare)
#pragma unroll
        for (int i = 0; i < 16; i++) {
            int c = t + i * 256;
            sEx[c] = dot64((const float4*)sDp, spb + (size_t)c * RR);
        }
        __syncthreads();
        if (t == 0) {
            unsigned int bk[16]; float bv[16]; int bc[16];
            int cnt = 0;
            for (int c = 0; c < NN; c++) {
                float val = sEx[c];
                unsigned int key = __float_as_uint(val) & 0x7fffffffu;
                if (cnt == 16 && key <= bk[15]) continue;
                int pos = (cnt < 16) ? cnt : 15;
                while (pos > 0 && bk[pos - 1] < key) {
                    bk[pos] = bk[pos - 1]; bv[pos] = bv[pos - 1]; bc[pos] = bc[pos - 1];
                    pos--;
                }
                bk[pos] = key; bv[pos] = val; bc[pos] = c;
                if (cnt < 16) cnt++;
            }
            for (int k = 0; k < KK; k++) {
                wOut[row * KK + k] = bv[k];
                idxOut[row * KK + k] = bc[k];
            }
        }
    }
}

// ---------------- fused message aggregation + optional residual layernorm ----------------
__global__ void __launch_bounds__(256) msg_kernel(const float* __restrict__ w,
                                                  const int* __restrict__ idx,
                                                  const float* __restrict__ srcval, int srcB,
                                                  const float* __restrict__ state,
                                                  const float* __restrict__ res, int resMod,
                                                  const float* __restrict__ g,
                                                  const float* __restrict__ bt,
                                                  float* __restrict__ outVal,
                                                  float* __restrict__ dstate) {
    __shared__ float sW[16];
    __shared__ int sI[16];
    __shared__ float sNorm[16];
    size_t row = blockIdx.x;
    int b = (int)(row >> 12);
    int t = threadIdx.x;
    if (t < 16) { sW[t] = w[row * KK + t]; sI[t] = idx[row * KK + t]; }
    __syncthreads();
    if (t == 0) {
        float mx = 0.f;
        for (int k = 0; k < 16; k++) mx = fmaxf(mx, fabsf(sW[k]));
        float e[16];
        float s = 0.f;
        for (int k = 0; k < 16; k++) { e[k] = expf(fabsf(sW[k]) - mx); s += e[k]; }
        float inv = 1.f / s;
        float dsum = 0.f;
        for (int k = 0; k < 16; k++) {
            float u = sW[k];
            float sg = (u > 0.f) ? 1.f : ((u < 0.f) ? -1.f : 0.f);
            float wt = sg * e[k] * inv;
            if (state) {
                float st = state[(size_t)b * NN + sI[k]];
                float sp = fmaxf(st, 0.f) + log1pf(expf(-fabsf(st)));  // softplus
                wt *= sp;
            }
            sW[k] = wt;
            dsum += wt;
        }
        dstate[row] = dsum;
    }
    __syncthreads();
    const float* base = srcval + (srcB ? 0 : (size_t)b * NN * DD);
    int wid = t >> 5, lid = t & 31;
    for (int k = wid; k < 16; k += 8) {
        const float* v = base + (size_t)sI[k] * DD;
        float ss = 0.f;
#pragma unroll
        for (int i = lid; i < 256; i += 32) { float x = v[i]; ss += x * x; }
        ss = warpSum(ss);
        if (lid == 0) sNorm[k] = sqrtf(ss) + 1e-6f;
    }
    __syncthreads();
    float acc = 0.f;
#pragma unroll
    for (int k = 0; k < 16; k++) {
        const float* v = base + (size_t)sI[k] * DD;
        acc = fmaf(sW[k] / sNorm[k], v[t], acc);
    }
    if (g) {
        int srow = resMod ? (int)(row & (resMod - 1)) : (int)row;
        float v = res[(size_t)srow * DD + t] + acc;
        float mean = blockSum256(v) * (1.f / DD);
        float d = v - mean;
        float var = blockSum256(d * d) * (1.f / DD);
        outVal[row * (size_t)DD + t] = d * rsqrtf(var + 1e-5f) * g[t] + bt[t];
    } else {
        outVal[row * (size_t)DD + t] = acc;
    }
}

// ---------------- host orchestration ----------------
extern "C" void kernel_launch(void* const* d_in, const int* in_sizes, int n_in,
                              void* d_out, int out_size) {
    const float* b_state    = (const float*)d_in[0];
    const float* b_val      = (const float*)d_in[1];
    const float* init_state = (const float*)d_in[2];
    const float* init_val   = (const float*)d_in[3];
    const float* U_bk = (const float*)d_in[4];
    const float* V_bk = (const float*)d_in[5];
    const float* U_kb = (const float*)d_in[6];
    const float* V_kb = (const float*)d_in[7];
    const float* U_p  = (const float*)d_in[8];
    const float* V_p  = (const float*)d_in[9];
    const float* kn_g = (const float*)d_in[10];
    const float* kn_b = (const float*)d_in[11];
    const float* bn_g = (const float*)d_in[12];
    const float* bn_b = (const float*)d_in[13];
    const float* pn_g = (const float*)d_in[14];
    const float* pn_b = (const float*)d_in[15];

    float* out = (float*)d_out;
    float* o_rstate = out;
    float* o_rval   = o_rstate + (size_t)BB * NN;
    float* o_pstate = o_rval + (size_t)BB * NN * DD;
    float* o_pval   = o_pstate + (size_t)BB * NN;
    float* o_bds    = o_pval + (size_t)BB * NN * DD;
    float* o_bdv    = o_bds + (size_t)BB * NN;

    float *p_scores, *p_spf, *p_dpf, *p_w, *p_kstate, *p_kval, *p_nk, *p_nv, *p_nb, *p_ds;
    __nv_bfloat16 *p_sph, *p_dph;
    int* p_idx;
    cudaGetSymbolAddress((void**)&p_scores, g_scores);
    cudaGetSymbolAddress((void**)&p_spf, g_spf);
    cudaGetSymbolAddress((void**)&p_dpf, g_dpf);
    cudaGetSymbolAddress((void**)&p_sph, g_sph);
    cudaGetSymbolAddress((void**)&p_dph, g_dph);
    cudaGetSymbolAddress((void**)&p_w, g_w);
    cudaGetSymbolAddress((void**)&p_idx, g_idx);
    cudaGetSymbolAddress((void**)&p_kstate, g_kstate);
    cudaGetSymbolAddress((void**)&p_kval, g_kval);
    cudaGetSymbolAddress((void**)&p_nk, g_nk);
    cudaGetSymbolAddress((void**)&p_nv, g_nv);
    cudaGetSymbolAddress((void**)&p_nb, g_nb);
    cudaGetSymbolAddress((void**)&p_ds, g_ds);

    dim3 mmaGrid(NN / 64, BB);

    // --- init ---
    ss_kernel<<<1, 256>>>(init_state, 1, nullptr, p_kstate);
    ln_kernel<<<NN, 256>>>(init_val, 0, nullptr, kn_g, kn_b, p_kval);
    ln_kernel<<<NN, 256>>>(p_kval, 0, nullptr, kn_g, kn_b, p_nk);

    // --- transition 1: B -> K ---
    proj_kernel<<<(BB * NN * 16) / 256, 256>>>(b_val, U_bk, p_spf, p_sph, BB * NN);
    proj_kernel<<<(NN * 16) / 256, 256>>>(p_nk, V_bk, p_dpf, p_dph, NN);
    wmma_score_kernel<<<mmaGrid, 256>>>(p_dph, p_sph, p_scores, 1, 0);
    topk_kernel<<<BB * NN, 256>>>(p_scores, p_dpf, p_spf, 1, 0, p_w, p_idx);
    msg_kernel<<<BB * NN, 256>>>(p_w, p_idx, b_val, 0, b_state,
                                 p_kval, NN, kn_g, kn_b, o_rval, p_ds);
    ss_kernel<<<BB, 256>>>(p_kstate, 1, p_ds, o_rstate);

    // --- propagation ---
    ln_kernel<<<BB * NN, 256>>>(o_rval, 0, nullptr, pn_g, pn_b, p_nv);
    proj_kernel<<<(BB * NN * 16) / 256, 256>>>(p_nv, U_p, p_spf, p_sph, BB * NN);
    proj_kernel<<<(BB * NN * 16) / 256, 256>>>(p_nv, V_p, p_dpf, p_dph, BB * NN);
    wmma_score_kernel<<<mmaGrid, 256>>>(p_dph, p_sph, p_scores, 0, 0);
    topk_kernel<<<BB * NN, 256>>>(p_scores, p_dpf, p_spf, 0, 0, p_w, p_idx);
    msg_kernel<<<BB * NN, 256>>>(p_w, p_idx, p_nv, 0, nullptr,
                                 o_rval, 0, kn_g, kn_b, o_pval, p_ds);
    ss_kernel<<<BB, 256>>>(o_rstate, 0, p_ds, o_pstate);

    // --- transition 2: K -> B (delta only) ---
    ln_kernel<<<BB * NN, 256>>>(o_pval, 0, nullptr, kn_g, kn_b, p_nv); // nk2
    ln_kernel<<<BB * NN, 256>>>(b_val, 0, nullptr, bn_g, bn_b, p_nb);  // nb
    proj_kernel<<<(BB * NN * 16) / 256, 256>>>(p_nv, U_kb, p_spf, p_sph, BB * NN);
    proj_kernel<<<(BB * NN * 16) / 256, 256>>>(p_nb, V_kb, p_dpf, p_dph, BB * NN);
    wmma_score_kernel<<<mmaGrid, 256>>>(p_dph, p_sph, p_scores, 0, 0);
    topk_kernel<<<BB * NN, 256>>>(p_scores, p_dpf, p_spf, 0, 0, p_w, p_idx);
    msg_kernel<<<BB * NN, 256>>>(p_w, p_idx, p_nv, 0, o_pstate,
                                 nullptr, 0, nullptr, nullptr, o_bdv, o_bds);
}

// round 14
// speedup vs baseline: 2.8821x; 1.0084x over previous
#include <cuda_runtime.h>
#include <cuda_bf16.h>
#include <mma.h>
#include <cstdint>
#include <cstddef>

#define BB 4
#define NN 4096
#define DD 256
#define RR 64
#define KK 16

// ---------------- device scratch (static; no runtime allocation) ----------------
__device__ __nv_bfloat16 g_scores[(size_t)BB * NN * NN];   // 128 MB approx scores (filter only)
__device__ float g_spf[(size_t)BB * NN * RR];
__device__ float g_dpf[(size_t)BB * NN * RR];
__device__ __nv_bfloat16 g_sph[(size_t)BB * NN * RR];
__device__ __nv_bfloat16 g_dph[(size_t)BB * NN * RR];
__device__ float g_w[(size_t)BB * NN * KK];
__device__ int   g_idx[(size_t)BB * NN * KK];
__device__ float g_kstate[NN];
__device__ float g_kval[(size_t)NN * DD];
__device__ float g_nk[(size_t)NN * DD];
__device__ float g_nv[(size_t)BB * NN * DD];
__device__ float g_nb[(size_t)BB * NN * DD];
__device__ float g_ds[(size_t)BB * NN];

// ---------------- reductions ----------------
__device__ __forceinline__ float warpSum(float v) {
#pragma unroll
    for (int o = 16; o > 0; o >>= 1) v += __shfl_xor_sync(0xffffffffu, v, o);
    return v;
}
__device__ __forceinline__ float warpMax(float v) {
#pragma unroll
    for (int o = 16; o > 0; o >>= 1) v = fmaxf(v, __shfl_xor_sync(0xffffffffu, v, o));
    return v;
}
__device__ __forceinline__ float blockSum256(float v) {
    __shared__ float sh[8];
    int wid = threadIdx.x >> 5, lid = threadIdx.x & 31;
    v = warpSum(v);
    if (lid == 0) sh[wid] = v;
    __syncthreads();
    float r = sh[0] + sh[1] + sh[2] + sh[3] + sh[4] + sh[5] + sh[6] + sh[7];
    __syncthreads();
    return r;
}
__device__ __forceinline__ float blockMax256(float v) {
    __shared__ float sh[8];
    int wid = threadIdx.x >> 5, lid = threadIdx.x & 31;
    v = warpMax(v);
    if (lid == 0) sh[wid] = v;
    __syncthreads();
    float r = fmaxf(fmaxf(fmaxf(sh[0], sh[1]), fmaxf(sh[2], sh[3])),
                    fmaxf(fmaxf(sh[4], sh[5]), fmaxf(sh[6], sh[7])));
    __syncthreads();
    return r;
}

// ---------------- layernorm over rows of 256 ----------------
__global__ void __launch_bounds__(256) ln_kernel(const float* __restrict__ x, int srcMod,
                                                 const float* __restrict__ res,
                                                 const float* __restrict__ g,
                                                 const float* __restrict__ bt,
                                                 float* __restrict__ out) {
    int row = blockIdx.x;
    int srow = srcMod ? (row & (srcMod - 1)) : row;
    int t = threadIdx.x;
    float v = x[(size_t)srow * DD + t];
    if (res) v += res[(size_t)row * DD + t];
    float mean = blockSum256(v) * (1.f / DD);
    float d = v - mean;
    float var = blockSum256(d * d) * (1.f / DD);
    out[(size_t)row * DD + t] = d * rsqrtf(var + 1e-5f) * g[t] + bt[t];
}

// ---------------- signed softmax over rows of 4096 ----------------
__global__ void __launch_bounds__(256) ss_kernel(const float* __restrict__ x, int xB,
                                                 const float* __restrict__ add,
                                                 float* __restrict__ out) {
    int b = blockIdx.x;
    const float* xr = x + (xB ? 0 : (size_t)b * NN);
    const float* ar = add ? add + (size_t)b * NN : nullptr;
    int t = threadIdx.x;
    float v[16];
    float mx = 0.f;
#pragma unroll
    for (int i = 0; i < 16; i++) {
        float u = xr[t + 256 * i];
        if (ar) u += ar[t + 256 * i];
        v[i] = u;
        mx = fmaxf(mx, fabsf(u));
    }
    mx = blockMax256(mx);
    float s = 0.f;
#pragma unroll
    for (int i = 0; i < 16; i++) s += expf(fabsf(v[i]) - mx);
    s = blockSum256(s);
    float inv = 1.f / s;
#pragma unroll
    for (int i = 0; i < 16; i++) {
        float u = v[i];
        float sg = (u > 0.f) ? 1.f : ((u < 0.f) ? -1.f : 0.f);
        out[(size_t)b * NN + t + 256 * i] = sg * expf(fabsf(u) - mx) * inv;
    }
}

// ---------------- projection: X[rows,256] @ W[256,64] -> fp32 + bf16(hi) ----------------
__global__ void __launch_bounds__(256) proj_kernel(const float* __restrict__ X,
                                                   const float* __restrict__ W,
                                                   float* __restrict__ outF,
                                                   __nv_bfloat16* __restrict__ outH,
                                                   int nrows) {
    int gi = blockIdx.x * 256 + threadIdx.x;
    int row = gi >> 4, cq = gi & 15;
    if (row >= nrows) return;
    const float4* W4 = (const float4*)W;
    const float4* X4 = (const float4*)(X + (size_t)row * DD);
    float4 acc = make_float4(0.f, 0.f, 0.f, 0.f);
#pragma unroll 8
    for (int d4 = 0; d4 < 64; d4++) {
        float4 xv = X4[d4];
        float4 w;
        w = W4[(d4 * 4 + 0) * 16 + cq];
        acc.x = fmaf(xv.x, w.x, acc.x); acc.y = fmaf(xv.x, w.y, acc.y);
        acc.z = fmaf(xv.x, w.z, acc.z); acc.w = fmaf(xv.x, w.w, acc.w);
        w = W4[(d4 * 4 + 1) * 16 + cq];
        acc.x = fmaf(xv.y, w.x, acc.x); acc.y = fmaf(xv.y, w.y, acc.y);
        acc.z = fmaf(xv.y, w.z, acc.z); acc.w = fmaf(xv.y, w.w, acc.w);
        w = W4[(d4 * 4 + 2) * 16 + cq];
        acc.x = fmaf(xv.z, w.x, acc.x); acc.y = fmaf(xv.z, w.y, acc.y);
        acc.z = fmaf(xv.z, w.z, acc.z); acc.w = fmaf(xv.z, w.w, acc.w);
        w = W4[(d4 * 4 + 3) * 16 + cq];
        acc.x = fmaf(xv.w, w.x, acc.x); acc.y = fmaf(xv.w, w.y, acc.y);
        acc.z = fmaf(xv.w, w.z, acc.z); acc.w = fmaf(xv.w, w.w, acc.w);
    }
    ((float4*)outF)[(size_t)row * 16 + cq] = acc;
    __nv_bfloat162 h0 = __nv_bfloat162(__float2bfloat16(acc.x), __float2bfloat16(acc.y));
    __nv_bfloat162 h1 = __nv_bfloat162(__float2bfloat16(acc.z), __float2bfloat16(acc.w));
    size_t base = (size_t)row * RR + cq * 4;
    __nv_bfloat162* oh = (__nv_bfloat162*)(outH + base);
    oh[0] = h0; oh[1] = h1;
}

// ---------------- WMMA approx score GEMM (hi-only), bf16 output ----------------
// CTA tile 64(n) x 128(m), grid (64, 4); fp32 tile staged through dead sB in halves.
#define LDS_B 72
#define LDS_S 68

using namespace nvcuda;

__global__ void __launch_bounds__(256) wmma_score_kernel(const __nv_bfloat16* __restrict__ dph,
                                                         const __nv_bfloat16* __restrict__ sph,
                                                         __nv_bfloat16* __restrict__ out,
                                                         int dpB, int spB) {
    __shared__ __nv_bfloat16 sA[64 * LDS_B];    //  9216 B
    __shared__ __nv_bfloat16 sB[128 * LDS_B];   // 18432 B (also reused as fp32 staging 64x68)
    float* sStage = (float*)sB;                 // 64 * 68 * 4 = 17408 <= 18432

    int t = threadIdx.x;
    int w = t >> 5;
    int wn = w & 1;            // 0..1 : n-subtile of 32
    int wm = w >> 1;           // 0..3 : m-subtile of 32
    int n0 = blockIdx.x * 64;
    int b = blockIdx.y;
    const __nv_bfloat16* dphb = dph + (dpB ? 0 : (size_t)b * NN * RR);
    const __nv_bfloat16* sphb = sph + (spB ? 0 : (size_t)b * NN * RR);

    // load resident A tile: 64 rows x 64 bf16
#pragma unroll
    for (int i = 0; i < 2; i++) {
        int s = t + i * 256;
        int r = s >> 3, q = s & 7;
        *(float4*)&sA[r * LDS_B + q * 8] = *(const float4*)(dphb + (size_t)(n0 + r) * RR + q * 8);
    }

    for (int mt = 0; mt < 32; mt++) {
        int m0 = mt * 128;
        __syncthreads();       // prev staging/conversion reads done before overwriting sB
#pragma unroll
        for (int i = 0; i < 4; i++) {
            int s = t + i * 256;
            int r = s >> 3, q = s & 7;
            *(float4*)&sB[r * LDS_B + q * 8] = *(const float4*)(sphb + (size_t)(m0 + r) * RR + q * 8);
        }
        __syncthreads();

        wmma::fragment<wmma::accumulator, 16, 16, 16, float> acc[2][2];
#pragma unroll
        for (int i = 0; i < 2; i++)
#pragma unroll
            for (int j = 0; j < 2; j++) wmma::fill_fragment(acc[i][j], 0.f);

#pragma unroll
        for (int ks = 0; ks < 4; ks++) {
            wmma::fragment<wmma::matrix_a, 16, 16, 16, __nv_bfloat16, wmma::row_major> a0, a1;
            wmma::fragment<wmma::matrix_b, 16, 16, 16, __nv_bfloat16, wmma::col_major> b0, b1;
            wmma::load_matrix_sync(a0, &sA[(wn * 32 + 0) * LDS_B + ks * 16], LDS_B);
            wmma::load_matrix_sync(a1, &sA[(wn * 32 + 16) * LDS_B + ks * 16], LDS_B);
            wmma::load_matrix_sync(b0, &sB[(wm * 32 + 0) * LDS_B + ks * 16], LDS_B);
            wmma::load_matrix_sync(b1, &sB[(wm * 32 + 16) * LDS_B + ks * 16], LDS_B);
            wmma::mma_sync(acc[0][0], a0, b0, acc[0][0]);
            wmma::mma_sync(acc[0][1], a0, b1, acc[0][1]);
            wmma::mma_sync(acc[1][0], a1, b0, acc[1][0]);
            wmma::mma_sync(acc[1][1], a1, b1, acc[1][1]);
        }
#pragma unroll
        for (int i = 0; i < 2; i++)
#pragma unroll
            for (int j = 0; j < 2; j++)
#pragma unroll
                for (int e = 0; e < acc[i][j].num_elements; e++) acc[i][j].x[e] *= 0.125f;

        // two halves: stage fp32 64x64 into dead sB, convert to bf16, store coalesced
#pragma unroll
        for (int h = 0; h < 2; h++) {
            __syncthreads();   // MMA reads of sB done (h=0) / prev conversion reads done (h=1)
            if ((wm >> 1) == h) {
                int cm = wm & 1;   // 0..1 : 32-col subtile within half
#pragma unroll
                for (int i = 0; i < 2; i++)
#pragma unroll
                    for (int j = 0; j < 2; j++)
                        wmma::store_matrix_sync(&sStage[(wn * 32 + i * 16) * LDS_S + cm * 32 + j * 16],
                                                acc[i][j], LDS_S, wmma::mem_row_major);
            }
            __syncthreads();
#pragma unroll
            for (int p = 0; p < 2; p++) {
                int id = t + p * 256;    // 0..511
                int r = id >> 3;         // row 0..63
                int cg = id & 7;         // 8-col group
                const float* sp8 = &sStage[r * LDS_S + cg * 8];
                float4 v0 = *(const float4*)sp8;
                float4 v1 = *(const float4*)(sp8 + 4);
                __nv_bfloat162 o0 = __nv_bfloat162(__float2bfloat16(v0.x), __float2bfloat16(v0.y));
                __nv_bfloat162 o1 = __nv_bfloat162(__float2bfloat16(v0.z), __float2bfloat16(v0.w));
                __nv_bfloat162 o2 = __nv_bfloat162(__float2bfloat16(v1.x), __float2bfloat16(v1.y));
                __nv_bfloat162 o3 = __nv_bfloat162(__float2bfloat16(v1.z), __float2bfloat16(v1.w));
                uint4 pk;
                pk.x = *(unsigned int*)&o0; pk.y = *(unsigned int*)&o1;
                pk.z = *(unsigned int*)&o2; pk.w = *(unsigned int*)&o3;
                *(uint4*)(out + ((size_t)b * NN + n0 + r) * NN + m0 + h * 64 + cg * 8) = pk;
            }
        }
    }
}

// ---------------- top-16: bf16 approx filter (8% margin) + EXACT fp32 re-score ----------------
__device__ __forceinline__ float dot64(const float4* a4, const float* bp) {
    const float4* b4 = (const float4*)bp;
    float s = 0.f;
#pragma unroll
    for (int q = 0; q < 16; q++) {
        float4 a = a4[q], b = b4[q];
        s = fmaf(a.x, b.x, s); s = fmaf(a.y, b.y, s);
        s = fmaf(a.z, b.z, s); s = fmaf(a.w, b.w, s);
    }
    return s * 0.125f;
}

__global__ void __launch_bounds__(256) topk_kernel(const __nv_bfloat16* __restrict__ approx,
                                                   const float* __restrict__ dpf,
                                                   const float* __restrict__ spf,
                                                   int dpB, int spB,
                                                   float* __restrict__ wOut,
                                                   int* __restrict__ idxOut) {
    __shared__ float sEx[4096];          // fallback exact row (rarely used)
    __shared__ float sDp[64];
    __shared__ unsigned int sVal[256];
    __shared__ int sColA[256];
    __shared__ unsigned int warp2[8];
    __shared__ int sCnt;
    size_t row = blockIdx.x;
    int b = (int)(row >> 12);
    int n = (int)(row & (NN - 1));
    const __nv_bfloat16* sr = approx + row * (size_t)NN;
    const float* dpRow = dpf + (dpB ? 0 : (size_t)b * NN * RR) + (size_t)n * RR;
    const float* spb = spf + (spB ? 0 : (size_t)b * NN * RR);
    int t = threadIdx.x;
    int lid = t & 31, wid = t >> 5;

    if (t < 16) ((float4*)sDp)[t] = ((const float4*)dpRow)[t];

    // 16 bf16 scores per thread via two uint4 loads
    unsigned int kk[16];
#pragma unroll
    for (int i = 0; i < 2; i++) {
        uint4 v = ((const uint4*)sr)[t + i * 256];
        unsigned int ws[4] = {v.x, v.y, v.z, v.w};
#pragma unroll
        for (int h = 0; h < 4; h++) {
            kk[i * 8 + h * 2 + 0] = (ws[h] << 16) & 0x7fffffffu;
            kk[i * 8 + h * 2 + 1] = ws[h] & 0x7fff0000u;
        }
    }

    unsigned int m1 = 0u, m2 = 0u;
#pragma unroll
    for (int e = 0; e < 16; e++) {
        unsigned int k = kk[e];
        if (k > m1) { m2 = m1; m1 = k; }
        else if (k > m2) { m2 = k; }
    }
#pragma unroll
    for (int o = 16; o > 0; o >>= 1) {
        unsigned int o1 = __shfl_xor_sync(0xffffffffu, m1, o);
        unsigned int o2 = __shfl_xor_sync(0xffffffffu, m2, o);
        if (o1 > m1) { m2 = (m1 > o2) ? m1 : o2; m1 = o1; }
        else { m2 = (m2 > o1) ? m2 : o1; }
    }
    if (lid == 0) warp2[wid] = m2;
    if (t == 0) sCnt = 0;
    __syncthreads();
    unsigned int T = warp2[0];
#pragma unroll
    for (int u = 1; u < 8; u++) T = (warp2[u] < T) ? warp2[u] : T;
    unsigned int Tm = __float_as_uint(__uint_as_float(T) * 0.92f);

#pragma unroll
    for (int e = 0; e < 16; e++) {
        if (kk[e] >= Tm) {
            int p = atomicAdd(&sCnt, 1);
            if (p < 256) sColA[p] = (t + (e >> 3) * 256) * 8 + (e & 7);
        }
    }
    __syncthreads();
    int C = sCnt;
    if (C <= 256) {
        if (t < C) {
            int ci = sColA[t];
            float ex = dot64((const float4*)sDp, spb + (size_t)ci * RR);
            sVal[t] = __float_as_uint(ex);
        }
        __syncthreads();
        if (t < C) {
            unsigned int vb = sVal[t];
            unsigned int ki = vb & 0x7fffffffu;
            int ci = sColA[t];
            int rank = 0;
            for (int j = 0; j < C; j++) {
                unsigned int kj = sVal[j] & 0x7fffffffu;
                int cj = sColA[j];
                rank += (kj > ki) || (kj == ki && cj < ci);
            }
            if (rank < KK) {
                wOut[row * KK + rank] = __uint_as_float(vb);
                idxOut[row * KK + rank] = ci;
            }
        }
    } else {
#pragma unroll
        for (int i = 0; i < 16; i++) {
            int c = t + i * 256;
            sEx[c] = dot64((const float4*)sDp, spb + (size_t)c * RR);
        }
        __syncthreads();
        if (t == 0) {
            unsigned int bk[16]; float bv[16]; int bc[16];
            int cnt = 0;
            for (int c = 0; c < NN; c++) {
                float val = sEx[c];
                unsigned int key = __float_as_uint(val) & 0x7fffffffu;
                if (cnt == 16 && key <= bk[15]) continue;
                int pos = (cnt < 16) ? cnt : 15;
                while (pos > 0 && bk[pos - 1] < key) {
                    bk[pos] = bk[pos - 1]; bv[pos] = bv[pos - 1]; bc[pos] = bc[pos - 1];
                    pos--;
                }
                bk[pos] = key; bv[pos] = val; bc[pos] = c;
                if (cnt < 16) cnt++;
            }
            for (int k = 0; k < KK; k++) {
                wOut[row * KK + k] = bv[k];
                idxOut[row * KK + k] = bc[k];
            }
        }
    }
}

// ---------------- fused message aggregation + optional residual layernorm ----------------
__global__ void __launch_bounds__(256) msg_kernel(const float* __restrict__ w,
                                                  const int* __restrict__ idx,
                                                  const float* __restrict__ srcval, int srcB,
                                                  const float* __restrict__ state,
                                                  const float* __restrict__ res, int resMod,
                                                  const float* __restrict__ g,
                                                  const float* __restrict__ bt,
                                                  float* __restrict__ outVal,
                                                  float* __restrict__ dstate) {
    __shared__ float sW[16];
    __shared__ int sI[16];
    __shared__ float sNorm[16];
    size_t row = blockIdx.x;
    int b = (int)(row >> 12);
    int t = threadIdx.x;
    if (t < 16) { sW[t] = w[row * KK + t]; sI[t] = idx[row * KK + t]; }
    __syncthreads();
    if (t == 0) {
        float mx = 0.f;
        for (int k = 0; k < 16; k++) mx = fmaxf(mx, fabsf(sW[k]));
        float e[16];
        float s = 0.f;
        for (int k = 0; k < 16; k++) { e[k] = expf(fabsf(sW[k]) - mx); s += e[k]; }
        float inv = 1.f / s;
        float dsum = 0.f;
        for (int k = 0; k < 16; k++) {
            float u = sW[k];
            float sg = (u > 0.f) ? 1.f : ((u < 0.f) ? -1.f : 0.f);
            float wt = sg * e[k] * inv;
            if (state) {
                float st = state[(size_t)b * NN + sI[k]];
                float sp = fmaxf(st, 0.f) + log1pf(expf(-fabsf(st)));  // softplus
                wt *= sp;
            }
            sW[k] = wt;
            dsum += wt;
        }
        dstate[row] = dsum;
    }
    __syncthreads();
    const float* base = srcval + (srcB ? 0 : (size_t)b * NN * DD);
    int wid = t >> 5, lid = t & 31;
    for (int k = wid; k < 16; k += 8) {
        const float* v = base + (size_t)sI[k] * DD;
        float ss = 0.f;
#pragma unroll
        for (int i = lid; i < 256; i += 32) { float x = v[i]; ss += x * x; }
        ss = warpSum(ss);
        if (lid == 0) sNorm[k] = sqrtf(ss) + 1e-6f;
    }
    __syncthreads();
    float acc = 0.f;
#pragma unroll
    for (int k = 0; k < 16; k++) {
        const float* v = base + (size_t)sI[k] * DD;
        acc = fmaf(sW[k] / sNorm[k], v[t], acc);
    }
    if (g) {
        int srow = resMod ? (int)(row & (resMod - 1)) : (int)row;
        float v = res[(size_t)srow * DD + t] + acc;
        float mean = blockSum256(v) * (1.f / DD);
        float d = v - mean;
        float var = blockSum256(d * d) * (1.f / DD);
        outVal[row * (size_t)DD + t] = d * rsqrtf(var + 1e-5f) * g[t] + bt[t];
    } else {
        outVal[row * (size_t)DD + t] = acc;
    }
}

// ---------------- host orchestration ----------------
extern "C" void kernel_launch(void* const* d_in, const int* in_sizes, int n_in,
                              void* d_out, int out_size) {
    const float* b_state    = (const float*)d_in[0];
    const float* b_val      = (const float*)d_in[1];
    const float* init_state = (const float*)d_in[2];
    const float* init_val   = (const float*)d_in[3];
    const float* U_bk = (const float*)d_in[4];
    const float* V_bk = (const float*)d_in[5];
    const float* U_kb = (const float*)d_in[6];
    const float* V_kb = (const float*)d_in[7];
    const float* U_p  = (const float*)d_in[8];
    const float* V_p  = (const float*)d_in[9];
    const float* kn_g = (const float*)d_in[10];
    const float* kn_b = (const float*)d_in[11];
    const float* bn_g = (const float*)d_in[12];
    const float* bn_b = (const float*)d_in[13];
    const float* pn_g = (const float*)d_in[14];
    const float* pn_b = (const float*)d_in[15];

    float* out = (float*)d_out;
    float* o_rstate = out;
    float* o_rval   = o_rstate + (size_t)BB * NN;
    float* o_pstate = o_rval + (size_t)BB * NN * DD;
    float* o_pval   = o_pstate + (size_t)BB * NN;
    float* o_bds    = o_pval + (size_t)BB * NN * DD;
    float* o_bdv    = o_bds + (size_t)BB * NN;

    float *p_spf, *p_dpf, *p_w, *p_kstate, *p_kval, *p_nk, *p_nv, *p_nb, *p_ds;
    __nv_bfloat16 *p_scores, *p_sph, *p_dph;
    int* p_idx;
    cudaGetSymbolAddress((void**)&p_scores, g_scores);
    cudaGetSymbolAddress((void**)&p_spf, g_spf);
    cudaGetSymbolAddress((void**)&p_dpf, g_dpf);
    cudaGetSymbolAddress((void**)&p_sph, g_sph);
    cudaGetSymbolAddress((void**)&p_dph, g_dph);
    cudaGetSymbolAddress((void**)&p_w, g_w);
    cudaGetSymbolAddress((void**)&p_idx, g_idx);
    cudaGetSymbolAddress((void**)&p_kstate, g_kstate);
    cudaGetSymbolAddress((void**)&p_kval, g_kval);
    cudaGetSymbolAddress((void**)&p_nk, g_nk);
    cudaGetSymbolAddress((void**)&p_nv, g_nv);
    cudaGetSymbolAddress((void**)&p_nb, g_nb);
    cudaGetSymbolAddress((void**)&p_ds, g_ds);

    dim3 mmaGrid(NN / 64, BB);

    // --- init ---
    ss_kernel<<<1, 256>>>(init_state, 1, nullptr, p_kstate);
    ln_kernel<<<NN, 256>>>(init_val, 0, nullptr, kn_g, kn_b, p_kval);
    ln_kernel<<<NN, 256>>>(p_kval, 0, nullptr, kn_g, kn_b, p_nk);

    // --- transition 1: B -> K ---
    proj_kernel<<<(BB * NN * 16) / 256, 256>>>(b_val, U_bk, p_spf, p_sph, BB * NN);
    proj_kernel<<<(NN * 16) / 256, 256>>>(p_nk, V_bk, p_dpf, p_dph, NN);
    wmma_score_kernel<<<mmaGrid, 256>>>(p_dph, p_sph, p_scores, 1, 0);
    topk_kernel<<<BB * NN, 256>>>(p_scores, p_dpf, p_spf, 1, 0, p_w, p_idx);
    msg_kernel<<<BB * NN, 256>>>(p_w, p_idx, b_val, 0, b_state,
                                 p_kval, NN, kn_g, kn_b, o_rval, p_ds);
    ss_kernel<<<BB, 256>>>(p_kstate, 1, p_ds, o_rstate);

    // --- propagation ---
    ln_kernel<<<BB * NN, 256>>>(o_rval, 0, nullptr, pn_g, pn_b, p_nv);
    proj_kernel<<<(BB * NN * 16) / 256, 256>>>(p_nv, U_p, p_spf, p_sph, BB * NN);
    proj_kernel<<<(BB * NN * 16) / 256, 256>>>(p_nv, V_p, p_dpf, p_dph, BB * NN);
    wmma_score_kernel<<<mmaGrid, 256>>>(p_dph, p_sph, p_scores, 0, 0);
    topk_kernel<<<BB * NN, 256>>>(p_scores, p_dpf, p_spf, 0, 0, p_w, p_idx);
    msg_kernel<<<BB * NN, 256>>>(p_w, p_idx, p_nv, 0, nullptr,
                                 o_rval, 0, kn_g, kn_b, o_pval, p_ds);
    ss_kernel<<<BB, 256>>>(o_rstate, 0, p_ds, o_pstate);

    // --- transition 2: K -> B (delta only) ---
    ln_kernel<<<BB * NN, 256>>>(o_pval, 0, nullptr, kn_g, kn_b, p_nv); // nk2
    ln_kernel<<<BB * NN, 256>>>(b_val, 0, nullptr, bn_g, bn_b, p_nb);  // nb
    proj_kernel<<<(BB * NN * 16) / 256, 256>>>(p_nv, U_kb, p_spf, p_sph, BB * NN);
    proj_kernel<<<(BB * NN * 16) / 256, 256>>>(p_nb, V_kb, p_dpf, p_dph, BB * NN);
    wmma_score_kernel<<<mmaGrid, 256>>>(p_dph, p_sph, p_scores, 0, 0);
    topk_kernel<<<BB * NN, 256>>>(p_scores, p_dpf, p_spf, 0, 0, p_w, p_idx);
    msg_kernel<<<BB * NN, 256>>>(p_w, p_idx, p_nv, 0, o_pstate,
                                 nullptr, 0, nullptr, nullptr, o_bdv, o_bds);
}